// round 14
// baseline (speedup 1.0000x reference)
#include <cuda_runtime.h>
#include <cuda_bf16.h>
#include <math.h>
#include <stdint.h>

// Problem constants
#define B_    2
#define S_    2048
#define DIM_  2048
#define NH_   16
#define QLR_  768
#define KVLR_ 512
#define NOPE_ 128
#define ROPE_ 64
#define VDIM_ 128
#define IH_   16
#define IHD_  128
#define ITOPK_ 512
#define BS_   (B_*S_)   // 4096

// ---------------- scratch (device globals; no allocation allowed) -------------
__device__ float g_qr[BS_*QLR_];
__device__ float g_q[BS_*NH_*(NOPE_+ROPE_)];
__device__ float g_kvfull[BS_*(KVLR_+ROPE_)];
__device__ float g_kv[BS_*KVLR_];
__device__ float g_kpe[BS_*ROPE_];
__device__ float g_qabs[BS_*NH_*KVLR_];
__device__ float g_qi[BS_*IH_*IHD_];
__device__ float g_ki[BS_*IHD_];
__device__ float g_wts[BS_*IH_];
__device__ float g_iscore[B_*S_*S_];
__device__ int   g_topk[BS_*ITOPK_];
__device__ float g_omid[BS_*NH_*KVLR_];
__device__ float g_o2[BS_*NH_*VDIM_];
__device__ float g_wkvbT[16*512*128];            // transposed wkv_b[:, :128, :] -> [h][c][d]
__device__ __nv_bfloat16 g_khi[BS_*576];         // kv||kpe hi split
__device__ __nv_bfloat16 g_klo[BS_*576];         // kv||kpe lo split

// =================== helpers ==================================================
__device__ __forceinline__ uint32_t smem_u32(const void* p) {
    uint32_t a;
    asm("{ .reg .u64 t; cvta.to.shared.u64 t, %1; cvt.u32.u64 %0, t; }" : "=r"(a) : "l"(p));
    return a;
}
__device__ __forceinline__ uint32_t pack_hi(float x, float y) {
    __nv_bfloat162 p;
    p.x = __float2bfloat16_rn(x);
    p.y = __float2bfloat16_rn(y);
    return *(uint32_t*)&p;
}
__device__ __forceinline__ uint32_t pack_lo(float x, float y) {
    __nv_bfloat16 hx = __float2bfloat16_rn(x);
    __nv_bfloat16 hy = __float2bfloat16_rn(y);
    __nv_bfloat162 p;
    p.x = __float2bfloat16_rn(x - __bfloat162float(hx));
    p.y = __float2bfloat16_rn(y - __bfloat162float(hy));
    return *(uint32_t*)&p;
}
__device__ __forceinline__ void mma16816(float* c, const uint32_t* a, const uint32_t* b) {
    asm volatile("mma.sync.aligned.m16n8k16.row.col.f32.bf16.bf16.f32 "
        "{%0,%1,%2,%3}, {%4,%5,%6,%7}, {%8,%9}, {%0,%1,%2,%3};"
        : "+f"(c[0]), "+f"(c[1]), "+f"(c[2]), "+f"(c[3])
        : "r"(a[0]), "r"(a[1]), "r"(a[2]), "r"(a[3]), "r"(b[0]), "r"(b[1]));
}
#define LDSM_X4(r, a) asm volatile("ldmatrix.sync.aligned.m8n8.x4.shared.b16 {%0,%1,%2,%3}, [%4];" \
    : "=r"((r)[0]),"=r"((r)[1]),"=r"((r)[2]),"=r"((r)[3]) : "r"(a))
#define LDSM_X2(r, a) asm volatile("ldmatrix.sync.aligned.m8n8.x2.shared.b16 {%0,%1}, [%2];" \
    : "=r"((r)[0]),"=r"((r)[1]) : "r"(a))
#define LDSM_X2T(r, a) asm volatile("ldmatrix.sync.aligned.m8n8.x2.trans.shared.b16 {%0,%1}, [%2];" \
    : "=r"((r)[0]),"=r"((r)[1]) : "r"(a))
#define CP_ASYNC16(dst, src) asm volatile("cp.async.cg.shared.global [%0], [%1], 16;" :: "r"(dst), "l"(src))
#define CP_COMMIT() asm volatile("cp.async.commit_group;" ::: "memory")
#define CP_WAIT(n)  asm volatile("cp.async.wait_group %0;" :: "n"(n) : "memory")

// word-granularity swizzled smem address for gemm_mma tiles (128 rows x 16 words)
__device__ __forceinline__ int sw_addr(int row, int w) {
    return row*16 + (w ^ ((((row)>>1)&3)<<2));
}

// =================== tensor-core GEMM (bf16x3): C[M,N]=A[M,K]@B[N,K]^T ========
#define GM_SMEM 65536

__global__ void __launch_bounds__(256, 1)
gemm_mma(const float* __restrict__ A, int lda, long aZ,
         const float* __restrict__ Bm, int ldb, long bZ,
         float* __restrict__ C, int ldc, long cZ,
         int M, int N, int K) {
    extern __shared__ uint32_t smw[];
    A  += (long)blockIdx.z * aZ;
    Bm += (long)blockIdx.z * bZ;
    C  += (long)blockIdx.z * cZ;
    int m0 = blockIdx.y * 128, n0 = blockIdx.x * 128;
    int tid = threadIdx.x, lane = tid & 31, wid = tid >> 5;
    int wm = wid >> 2, wn = wid & 3;
    int g = lane >> 2, tig = lane & 3;

    float acc[4][4][4];
#pragma unroll
    for (int i = 0; i < 4; i++)
#pragma unroll
        for (int j = 0; j < 4; j++)
#pragma unroll
            for (int r = 0; r < 4; r++) acc[i][j][r] = 0.f;

    int arow = tid >> 1, acol = (tid & 1) * 16;
    int nch = K >> 5;

    float4 ra[4], rb[4];
    {
        const float* ap = A + (long)(m0 + arow)*lda + acol;
        bool aok = (m0 + arow) < M;
#pragma unroll
        for (int i = 0; i < 4; i++)
            ra[i] = aok ? *(const float4*)(ap + i*4) : make_float4(0.f,0.f,0.f,0.f);
        const float* bp = Bm + (long)(n0 + arow)*ldb + acol;
        bool bok = (n0 + arow) < N;
#pragma unroll
        for (int i = 0; i < 4; i++)
            rb[i] = bok ? *(const float4*)(bp + i*4) : make_float4(0.f,0.f,0.f,0.f);
    }

    for (int it = 0; it < nch; it++) {
        int stg = it & 1;
        uint32_t* sAhi = smw + stg*8192;
        uint32_t* sAlo = sAhi + 2048;
        uint32_t* sBhi = sAhi + 4096;
        uint32_t* sBlo = sAhi + 6144;
        {
            uint32_t hw[8], lw[8];
#pragma unroll
            for (int i = 0; i < 4; i++) {
                hw[i*2]   = pack_hi(ra[i].x, ra[i].y);
                hw[i*2+1] = pack_hi(ra[i].z, ra[i].w);
                lw[i*2]   = pack_lo(ra[i].x, ra[i].y);
                lw[i*2+1] = pack_lo(ra[i].z, ra[i].w);
            }
            int g0 = (((tid&1)*2 + 0) ^ ((arow>>1)&3)) * 4;
            int g1 = (((tid&1)*2 + 1) ^ ((arow>>1)&3)) * 4;
            uint32_t* dst = sAhi + arow*16;
            *(uint4*)(dst + g0) = make_uint4(hw[0],hw[1],hw[2],hw[3]);
            *(uint4*)(dst + g1) = make_uint4(hw[4],hw[5],hw[6],hw[7]);
            dst = sAlo + arow*16;
            *(uint4*)(dst + g0) = make_uint4(lw[0],lw[1],lw[2],lw[3]);
            *(uint4*)(dst + g1) = make_uint4(lw[4],lw[5],lw[6],lw[7]);
#pragma unroll
            for (int i = 0; i < 4; i++) {
                hw[i*2]   = pack_hi(rb[i].x, rb[i].y);
                hw[i*2+1] = pack_hi(rb[i].z, rb[i].w);
                lw[i*2]   = pack_lo(rb[i].x, rb[i].y);
                lw[i*2+1] = pack_lo(rb[i].z, rb[i].w);
            }
            dst = sBhi + arow*16;
            *(uint4*)(dst + g0) = make_uint4(hw[0],hw[1],hw[2],hw[3]);
            *(uint4*)(dst + g1) = make_uint4(hw[4],hw[5],hw[6],hw[7]);
            dst = sBlo + arow*16;
            *(uint4*)(dst + g0) = make_uint4(lw[0],lw[1],lw[2],lw[3]);
            *(uint4*)(dst + g1) = make_uint4(lw[4],lw[5],lw[6],lw[7]);
        }
        __syncthreads();
        if (it + 1 < nch) {
            int gk = (it + 1) << 5;
            const float* ap = A + (long)(m0 + arow)*lda + gk + acol;
            bool aok = (m0 + arow) < M;
#pragma unroll
            for (int i = 0; i < 4; i++)
                ra[i] = aok ? *(const float4*)(ap + i*4) : make_float4(0.f,0.f,0.f,0.f);
            const float* bp = Bm + (long)(n0 + arow)*ldb + gk + acol;
            bool bok = (n0 + arow) < N;
#pragma unroll
            for (int i = 0; i < 4; i++)
                rb[i] = bok ? *(const float4*)(bp + i*4) : make_float4(0.f,0.f,0.f,0.f);
        }
#pragma unroll
        for (int ks = 0; ks < 2; ks++) {
            uint32_t bh[4][2], bl[4][2];
#pragma unroll
            for (int nt = 0; nt < 4; nt++) {
                int nrow = wn*32 + nt*8 + g;
                int w0 = ks*8 + tig;
                bh[nt][0] = sBhi[sw_addr(nrow, w0)];
                bh[nt][1] = sBhi[sw_addr(nrow, w0+4)];
                bl[nt][0] = sBlo[sw_addr(nrow, w0)];
                bl[nt][1] = sBlo[sw_addr(nrow, w0+4)];
            }
#pragma unroll
            for (int mt = 0; mt < 4; mt++) {
                int ar = wm*64 + mt*16 + g;
                int w0 = ks*8 + tig;
                uint32_t ah[4], al[4];
                ah[0] = sAhi[sw_addr(ar,   w0)];
                ah[1] = sAhi[sw_addr(ar+8, w0)];
                ah[2] = sAhi[sw_addr(ar,   w0+4)];
                ah[3] = sAhi[sw_addr(ar+8, w0+4)];
                al[0] = sAlo[sw_addr(ar,   w0)];
                al[1] = sAlo[sw_addr(ar+8, w0)];
                al[2] = sAlo[sw_addr(ar,   w0+4)];
                al[3] = sAlo[sw_addr(ar+8, w0+4)];
#pragma unroll
                for (int nt = 0; nt < 4; nt++) {
                    mma16816(acc[mt][nt], ah, bh[nt]);
                    mma16816(acc[mt][nt], ah, bl[nt]);
                    mma16816(acc[mt][nt], al, bh[nt]);
                }
            }
        }
        __syncthreads();
    }
#pragma unroll
    for (int mt = 0; mt < 4; mt++) {
#pragma unroll
        for (int nt = 0; nt < 4; nt++) {
            int r0 = m0 + wm*64 + mt*16 + g;
            int c0 = n0 + wn*32 + nt*8 + tig*2;
            if (c0 < N) {
                if (r0 < M)
                    *(float2*)(C + (long)r0*ldc + c0) = make_float2(acc[mt][nt][0], acc[mt][nt][1]);
                if (r0 + 8 < M)
                    *(float2*)(C + (long)(r0+8)*ldc + c0) = make_float2(acc[mt][nt][2], acc[mt][nt][3]);
            }
        }
    }
}

// transpose wkv_b[:, :128, :] -> wt[h][c][d]
__global__ void transpose_wkvb(const float* __restrict__ w, float* __restrict__ wt) {
    int idx = blockIdx.x * 256 + threadIdx.x;
    if (idx >= 16*128*512) return;
    int c = idx & 511, d = (idx >> 9) & 127, h = idx >> 16;
    wt[h*65536 + c*128 + d] = w[h*131072 + d*512 + c];
}

// ---------------- fp32 GEMM (bit-exact k-order, float4 loads) ------------------
__global__ void __launch_bounds__(256)
gemm_bt(const float* __restrict__ A, int lda, long aZ,
        const float* __restrict__ Bm, int ldb, long bZ,
        float* __restrict__ C, int ldc, long cZ,
        int M, int N, int K) {
    A  += (long)blockIdx.z * aZ;
    Bm += (long)blockIdx.z * bZ;
    C  += (long)blockIdx.z * cZ;
    int n0 = blockIdx.x * 128, m0 = blockIdx.y * 128;
    __shared__ float As[16][129];
    __shared__ float Bs[16][129];
    int tid = threadIdx.x;
    int tx = tid & 15, ty = tid >> 4;
    int lq = tid & 3, lm = tid >> 2;     // float4 load indices: k-quad, row
    float acc[8][8];
#pragma unroll
    for (int i = 0; i < 8; i++)
#pragma unroll
        for (int j = 0; j < 8; j++) acc[i][j] = 0.f;

    for (int k0 = 0; k0 < K; k0 += 16) {
#pragma unroll
        for (int p = 0; p < 2; p++) {
            int m = lm + 64*p;
            float4 va = *(const float4*)(A + (long)(m0 + m)*lda + k0 + lq*4);
            As[lq*4+0][m] = va.x; As[lq*4+1][m] = va.y;
            As[lq*4+2][m] = va.z; As[lq*4+3][m] = va.w;
            int gn = n0 + m;
            float4 vb = (gn < N) ? *(const float4*)(Bm + (long)gn*ldb + k0 + lq*4)
                                 : make_float4(0.f,0.f,0.f,0.f);
            Bs[lq*4+0][m] = vb.x; Bs[lq*4+1][m] = vb.y;
            Bs[lq*4+2][m] = vb.z; Bs[lq*4+3][m] = vb.w;
        }
        __syncthreads();
#pragma unroll
        for (int kk = 0; kk < 16; kk++) {
            float a[8], bb[8];
#pragma unroll
            for (int i = 0; i < 8; i++) a[i]  = As[kk][ty + 16*i];
#pragma unroll
            for (int j = 0; j < 8; j++) bb[j] = Bs[kk][tx + 16*j];
#pragma unroll
            for (int i = 0; i < 8; i++)
#pragma unroll
                for (int j = 0; j < 8; j++) acc[i][j] += a[i]*bb[j];
        }
        __syncthreads();
    }
#pragma unroll
    for (int i = 0; i < 8; i++)
#pragma unroll
        for (int j = 0; j < 8; j++) {
            int gm = m0 + ty + 16*i, gn = n0 + tx + 16*j;
            if (gm < M && gn < N) C[(long)gm*ldc + gn] = acc[i][j];
        }
}

// ---------------- elementwise / norm / rope -----------------------------------
__global__ void rmsnorm_kernel(float* __restrict__ x, const float* __restrict__ w, int L) {
    int row = blockIdx.x, tid = threadIdx.x;
    float* pr = x + (long)row * L;
    float ss = 0.f;
    for (int i = tid; i < L; i += 256) { float v = pr[i]; ss += v*v; }
    __shared__ float red[256];
    red[tid] = ss; __syncthreads();
    for (int o = 128; o > 0; o >>= 1) { if (tid < o) red[tid] += red[tid+o]; __syncthreads(); }
    float inv = rsqrtf(red[0] / (float)L + 1e-6f);
    for (int i = tid; i < L; i += 256) pr[i] = w[i] * pr[i] * inv;
}

__global__ void kvpost_kernel(const float* __restrict__ kvfull, const float* __restrict__ w,
                              const float* __restrict__ fcos, const float* __restrict__ fsin,
                              float* __restrict__ kv, float* __restrict__ kpe) {
    int row = blockIdx.x, s = row & (S_-1), tid = threadIdx.x;
    const float* src = kvfull + (long)row * 576;
    float ss = 0.f;
    for (int i = tid; i < 512; i += 256) { float v = src[i]; ss += v*v; }
    __shared__ float red[256];
    red[tid] = ss; __syncthreads();
    for (int o = 128; o > 0; o >>= 1) { if (tid < o) red[tid] += red[tid+o]; __syncthreads(); }
    float inv = rsqrtf(red[0] / 512.f + 1e-6f);
    for (int i = tid; i < 512; i += 256) kv[(long)row*512 + i] = w[i] * src[i] * inv;
    if (tid < 32) {
        float x1 = src[512 + tid], x2 = src[544 + tid];
        float c = fcos[s*32 + tid], sn = fsin[s*32 + tid];
        kpe[(long)row*64 + tid]      = x1*c - x2*sn;
        kpe[(long)row*64 + 32 + tid] = x1*sn + x2*c;
    }
}

// split kv||kpe into bf16 hi/lo global arrays
__global__ void kvsplit_kernel(const float* __restrict__ kv, const float* __restrict__ kpe,
                               __nv_bfloat16* __restrict__ khi, __nv_bfloat16* __restrict__ klo) {
    int idx = blockIdx.x*256 + threadIdx.x;
    if (idx >= BS_*576) return;
    int r = idx / 576, d = idx - r*576;
    float v = (d < 512) ? kv[(long)r*512 + d] : kpe[(long)r*64 + d - 512];
    __nv_bfloat16 hi = __float2bfloat16_rn(v);
    khi[idx] = hi;
    klo[idx] = __float2bfloat16_rn(v - __bfloat162float(hi));
}

__global__ void kipost_kernel(float* __restrict__ ki, const float* __restrict__ w,
                              const float* __restrict__ bvec,
                              const float* __restrict__ fcos, const float* __restrict__ fsin) {
    int row = blockIdx.x, s = row & (S_-1), tid = threadIdx.x; // 128 threads
    float* pr = ki + (long)row * 128;
    float v = pr[tid];
    __shared__ float red[128];
    red[tid] = v; __syncthreads();
    for (int o = 64; o > 0; o >>= 1) { if (tid < o) red[tid] += red[tid+o]; __syncthreads(); }
    float mean = red[0] / 128.f;
    __syncthreads();
    float d = v - mean;
    red[tid] = d*d; __syncthreads();
    for (int o = 64; o > 0; o >>= 1) { if (tid < o) red[tid] += red[tid+o]; __syncthreads(); }
    float var = red[0] / 128.f;
    __syncthreads();
    float y = d * rsqrtf(var + 1e-6f) * w[tid] + bvec[tid];
    __shared__ float yb[128];
    yb[tid] = y; __syncthreads();
    float outv;
    if (tid < 32) {
        float c = fcos[s*32 + tid], sn = fsin[s*32 + tid];
        outv = yb[tid]*c - yb[tid+32]*sn;
    } else if (tid < 64) {
        int i = tid - 32;
        float c = fcos[s*32 + i], sn = fsin[s*32 + i];
        outv = yb[i]*sn + yb[tid]*c;
    } else {
        outv = y;
    }
    pr[tid] = outv;
}

__global__ void rope_q_kernel(float* __restrict__ q, const float* __restrict__ fcos,
                              const float* __restrict__ fsin) {
    int idx = blockIdx.x * blockDim.x + threadIdx.x;
    if (idx >= BS_*16*32) return;
    int i = idx & 31, h = (idx >> 5) & 15, bs = idx >> 9;
    int s = bs & (S_-1);
    long base = (long)bs*3072 + h*192 + 128;
    float x1 = q[base + i], x2 = q[base + 32 + i];
    float c = fcos[s*32 + i], sn = fsin[s*32 + i];
    q[base + i]      = x1*c - x2*sn;
    q[base + 32 + i] = x1*sn + x2*c;
}

// rope on qi[..., 0:64] per head; nrows rows starting at the given pointer
__global__ void rope_qi_kernel(float* __restrict__ qi, const float* __restrict__ fcos,
                               const float* __restrict__ fsin, int nrows) {
    int idx = blockIdx.x * blockDim.x + threadIdx.x;
    if (idx >= nrows*16*32) return;
    int i = idx & 31, h = (idx >> 5) & 15, bs = idx >> 9;
    int s = bs & (S_-1);
    long base = (long)bs*2048 + h*128;
    float x1 = qi[base + i], x2 = qi[base + 32 + i];
    float c = fcos[s*32 + i], sn = fsin[s*32 + i];
    qi[base + i]      = x1*c - x2*sn;
    qi[base + 32 + i] = x1*sn + x2*c;
}

// ---------------- indexer score (128s x 64t tile, 2 heads/pass, bit-exact) ----
// Rows start at s_base (rows s<512 are never read downstream and are skipped).
__global__ void __launch_bounds__(256)
iscore_kernel(const float* __restrict__ qi, const float* __restrict__ ki,
              const float* __restrict__ wts, float* __restrict__ iscore, int s_base) {
    int s0 = s_base + blockIdx.y * 128, t0 = blockIdx.x * 64;
    int tid = threadIdx.x;
    if (t0 > s0 + 127) return;   // fully-masked tile: never read downstream
    int tx = tid & 15, ty = tid >> 4;
    int lq = tid & 3, lm = tid >> 2;
    __shared__ float qs[2][16][129];
    __shared__ float ks[16][65];
    __shared__ float ws_s[16][128];
    const float IW_SCALE = rsqrtf(2048.0f);
    for (int i = tid; i < 16*128; i += 256) {
        int m = i >> 4, h = i & 15;
        ws_s[h][m] = wts[((long)(s0 + m))*16 + h] * IW_SCALE;
    }
    float acc[8][4];
#pragma unroll
    for (int i = 0; i < 8; i++)
#pragma unroll
        for (int j = 0; j < 4; j++) acc[i][j] = 0.f;
    __syncthreads();

    for (int h = 0; h < 16; h += 2) {
        float dot[2][8][4];
#pragma unroll
        for (int e = 0; e < 2; e++)
#pragma unroll
            for (int i = 0; i < 8; i++)
#pragma unroll
                for (int j = 0; j < 4; j++) dot[e][i][j] = 0.f;
        for (int d0 = 0; d0 < 128; d0 += 16) {
#pragma unroll
            for (int e = 0; e < 2; e++)
#pragma unroll
                for (int p = 0; p < 2; p++) {
                    int m = lm + 64*p;
                    float4 v = *(const float4*)(qi + ((long)(s0 + m))*2048 + (h+e)*128 + d0 + lq*4);
                    qs[e][lq*4+0][m] = v.x; qs[e][lq*4+1][m] = v.y;
                    qs[e][lq*4+2][m] = v.z; qs[e][lq*4+3][m] = v.w;
                }
            {
                float4 v = *(const float4*)(ki + ((long)(t0 + lm))*128 + d0 + lq*4);
                ks[lq*4+0][lm] = v.x; ks[lq*4+1][lm] = v.y;
                ks[lq*4+2][lm] = v.z; ks[lq*4+3][lm] = v.w;
            }
            __syncthreads();
#pragma unroll
            for (int kk = 0; kk < 16; kk++) {
                float a0[8], a1[8], bb[4];
#pragma unroll
                for (int i = 0; i < 8; i++) { a0[i] = qs[0][kk][ty + 16*i]; a1[i] = qs[1][kk][ty + 16*i]; }
#pragma unroll
                for (int j = 0; j < 4; j++) bb[j] = ks[kk][tx + 16*j];
#pragma unroll
                for (int i = 0; i < 8; i++)
#pragma unroll
                    for (int j = 0; j < 4; j++) {
                        dot[0][i][j] += a0[i]*bb[j];
                        dot[1][i][j] += a1[i]*bb[j];
                    }
            }
            __syncthreads();
        }
#pragma unroll
        for (int e = 0; e < 2; e++)
#pragma unroll
            for (int i = 0; i < 8; i++) {
                float w = ws_s[h+e][ty + 16*i];
#pragma unroll
                for (int j = 0; j < 4; j++) acc[i][j] += fmaxf(dot[e][i][j], 0.f) * w;
            }
    }
#pragma unroll
    for (int i = 0; i < 8; i++)
#pragma unroll
        for (int j = 0; j < 4; j++) {
            int s = s0 + ty + 16*i, t = t0 + tx + 16*j;
            float mval = (t <= s) ? 0.f : -1000000000.0f;
            iscore[((long)s)*S_ + t] = acc[i][j] + mval;
        }
}

// ---------------- exact top-512 per row (prefix-only radix, deterministic) ----
// Launched only for rows s >= 512 (s = blockIdx.x + s_off).
__global__ void topk_kernel(const float* __restrict__ iscore, int* __restrict__ out, int s_off) {
    int s = blockIdx.x + s_off;
    int tid = threadIdx.x; // 256
    int* o = out + (long)s * ITOPK_;
    const float* p = iscore + (long)s * S_;
    __shared__ unsigned int hist[256];
    __shared__ unsigned int s_prefix;
    __shared__ int s_rem;
    __shared__ int sgt[257], seq[257];
    if (tid == 0) { s_prefix = 0u; s_rem = ITOPK_; }
    __syncthreads();
    for (int pass = 0; pass < 4; pass++) {
        hist[tid] = 0u;
        __syncthreads();
        int shift = 24 - 8*pass;
        unsigned int pref = s_prefix;
        for (int e = 0; e < 8; e++) {
            int j = tid*8 + e;
            if (j > s) break;
            unsigned int u = __float_as_uint(p[j]);
            unsigned int k = (u & 0x80000000u) ? ~u : (u | 0x80000000u);
            bool ok = (pass == 0) || (((k ^ pref) >> (shift + 8)) == 0u);
            if (ok) atomicAdd(&hist[(k >> shift) & 255u], 1u);
        }
        __syncthreads();
        if (tid == 0) {
            int rem = s_rem;
            unsigned int cum = 0; int bin = 0;
            for (int bb = 255; bb >= 0; bb--) {
                if (cum + hist[bb] >= (unsigned)rem) { bin = bb; break; }
                cum += hist[bb];
            }
            s_rem = rem - (int)cum;
            s_prefix = s_prefix | ((unsigned)bin << shift);
        }
        __syncthreads();
    }
    unsigned int kth = s_prefix;
    int cgt = 0, ceq = 0;
    for (int e = 0; e < 8; e++) {
        int j = tid*8 + e;
        if (j > s) break;
        unsigned int u = __float_as_uint(p[j]);
        unsigned int k = (u & 0x80000000u) ? ~u : (u | 0x80000000u);
        cgt += (k > kth); ceq += (k == kth);
    }
    sgt[tid] = cgt; seq[tid] = ceq;
    __syncthreads();
    if (tid == 0) {
        int ag = 0, ae = 0;
        for (int i = 0; i < 256; i++) {
            int tg = sgt[i], te = seq[i];
            sgt[i] = ag; seq[i] = ae;
            ag += tg; ae += te;
        }
        sgt[256] = ag;
    }
    __syncthreads();
    int total_gt = sgt[256];
    int pgt = sgt[tid];
    int peq = total_gt + seq[tid];
    for (int e = 0; e < 8; e++) {
        int j = tid*8 + e;
        if (j > s) break;
        unsigned int u = __float_as_uint(p[j]);
        unsigned int k = (u & 0x80000000u) ? ~u : (u | 0x80000000u);
        if (k > kth) { o[pgt++] = j; }
        else if (k == kth) { if (peq < ITOPK_) o[peq] = j; peq++; }
    }
}

// ---------------- fused flash-style tensor-core sparse attention ---------------
// 512 threads / 16 warps, Q hi-fragments hoisted, all-invalid chunks skipped.
// Rows s<512 synthesize tl[j]=j (identical to topk output) -> no topk dependency.
#define AT_SMEM 200448
#define AT_BUF0 50944
#define AT_BUFSZ 74752
#define AT_LO 37376

__device__ __forceinline__ void at_gather(const __nv_bfloat16* __restrict__ khi,
                                          const __nv_bfloat16* __restrict__ klo,
                                          long kb, const int* tl, int c,
                                          uint32_t bufaddr, int tid) {
    int jloc = tid >> 4, sg0 = tid & 15;   // 32 rows x 16 threads
    int t = tl[c*32 + jloc];
    const char* sh = (const char*)(khi + kb + (long)t*576);
    const char* sl = (const char*)(klo + kb + (long)t*576);
    uint32_t dh = bufaddr + jloc*1168;
#pragma unroll
    for (int u = 0; u < 9; u++) {
        int ch = sg0 + u*16;               // 0..143: 72 hi chunks then 72 lo
        if (ch < 72) CP_ASYNC16(dh + ch*16, sh + ch*16);
        else         CP_ASYNC16(dh + AT_LO + (ch-72)*16, sl + (ch-72)*16);
    }
    CP_COMMIT();
}

__global__ void __launch_bounds__(512, 1)
attn_tc(const float* __restrict__ qabs, const float* __restrict__ qfull,
        const __nv_bfloat16* __restrict__ khi, const __nv_bfloat16* __restrict__ klo,
        const int* __restrict__ topk, float* __restrict__ omid, int b0, int s_off) {
    extern __shared__ char sm[];
    uint32_t sb = smem_u32(sm);
    int* tl = (int*)sm;
    float* m_s  = (float*)(sm + 2048);
    float* l_s  = (float*)(sm + 2112);
    float* al_s = (float*)(sm + 2176);
    float* sc   = (float*)(sm + 2304);       // [4][16][34]
    __nv_bfloat16* qh = (__nv_bfloat16*)(sm + 11008);
    __nv_bfloat16* ph = (__nv_bfloat16*)(sm + 48384);
    __nv_bfloat16* pl = (__nv_bfloat16*)(sm + 49664);
    int s = blockIdx.x + s_off;
    if (blockIdx.y) b0 = 1;                  // 2D early grid: y = batch
    int bs = b0*S_ + s;
    int tid = threadIdx.x, lane = tid & 31, w = tid >> 5;
    const long kb = (long)b0 * 2048 * 576;
    int nchk = (s >> 5) + 1;
    if (nchk > 16) nchk = 16;

    if (s < ITOPK_) {
        for (int j = tid; j < 512; j += 512) tl[j] = j;
    } else {
        for (int j = tid; j < 512; j += 512) tl[j] = topk[(long)bs*512 + j];
    }
    if (tid < 16) { m_s[tid] = -1e30f; l_s[tid] = 0.f; }
    const float scale = 0.07216878364870322f;  // 1/sqrt(192)
    __syncthreads();
    for (int i = tid; i < 16*576; i += 512) {
        int h = i / 576, d = i - h*576;
        float v = (d < 512) ? qabs[(long)bs*8192 + h*512 + d]
                            : qfull[(long)bs*3072 + h*192 + 128 + (d - 512)];
        v *= scale;
        __nv_bfloat16 hi = __float2bfloat16_rn(v);
        qh[h*584 + d] = hi;
        qh[9344 + h*584 + d] = __float2bfloat16_rn(v - __bfloat162float(hi));  // ql region
    }
    at_gather(khi, klo, kb, tl, 0, sb + AT_BUF0, tid);
    __syncthreads();

    float oacc[4][4];
#pragma unroll
    for (int nt = 0; nt < 4; nt++)
#pragma unroll
        for (int r = 0; r < 4; r++) oacc[nt][r] = 0.f;

    int kh4 = w >> 2, nt4 = w & 3;
    int arow = lane & 15, ac = (lane >> 4) * 8;
    int brow = nt4*8 + (lane & 7), bc = ((lane >> 3) & 1) * 8;

    uint32_t ahq[9][4];
#pragma unroll
    for (int ks = 0; ks < 9; ks++) {
        int d = kh4*144 + ks*16;
        uint32_t ad = sb + 11008 + (arow*584 + d + ac)*2;
        LDSM_X4(ahq[ks], ad);
    }

    for (int c = 0; c < nchk; c++) {
        uint32_t buf = sb + AT_BUF0 + (c & 1)*AT_BUFSZ;
        if (c + 1 < nchk) {
            at_gather(khi, klo, kb, tl, c+1, sb + AT_BUF0 + ((c+1)&1)*AT_BUFSZ, tid);
            CP_WAIT(1);
        } else {
            CP_WAIT(0);
        }
        __syncthreads();

        float qk[4] = {0.f, 0.f, 0.f, 0.f};
#pragma unroll
        for (int ks = 0; ks < 9; ks++) {
            int d = kh4*144 + ks*16;
            uint32_t alr[4], bh[2], bl[2];
            uint32_t ad = sb + 11008 + (arow*584 + d + ac)*2;
            LDSM_X4(alr, ad + 18688);
            uint32_t bd = buf + (brow*584 + d + bc)*2;
            LDSM_X2(bh, bd);
            LDSM_X2(bl, bd + AT_LO);
            mma16816(qk, ahq[ks], bh);
            mma16816(qk, ahq[ks], bl);
            mma16816(qk, alr, bh);
        }
        {
            int m_ = lane >> 2, e0 = 2*(lane & 3);
            float* scr = sc + kh4*544;
            scr[m_*34 + nt4*8 + e0]       = qk[0];
            scr[m_*34 + nt4*8 + e0 + 1]   = qk[1];
            scr[(m_+8)*34 + nt4*8 + e0]   = qk[2];
            scr[(m_+8)*34 + nt4*8 + e0+1] = qk[3];
        }
        __syncthreads();

        {
            int t = tl[c*32 + lane];
            bool valid = (t <= s);
            int hh = w;
            float v = sc[hh*34 + lane] + sc[544 + hh*34 + lane]
                    + sc[1088 + hh*34 + lane] + sc[1632 + hh*34 + lane];
            float val = valid ? v : -1e30f;
            float mc = val;
#pragma unroll
            for (int o = 16; o > 0; o >>= 1) mc = fmaxf(mc, __shfl_xor_sync(0xffffffffu, mc, o));
            float m_old = m_s[hh];
            float m_new = fmaxf(m_old, mc);
            float a = expf(m_old - m_new);
            float p = valid ? expf(val - m_new) : 0.f;
            float psum = p;
#pragma unroll
            for (int o = 16; o > 0; o >>= 1) psum += __shfl_xor_sync(0xffffffffu, psum, o);
            if (lane == 0) { m_s[hh] = m_new; l_s[hh] = l_s[hh]*a + psum; al_s[hh] = a; }
            __nv_bfloat16 phi = __float2bfloat16_rn(p);
            ph[hh*40 + lane] = phi;
            pl[hh*40 + lane] = __float2bfloat16_rn(p - __bfloat162float(phi));
        }
        __syncthreads();

        {
            float a0 = al_s[lane >> 2], a1 = al_s[(lane >> 2) + 8];
#pragma unroll
            for (int nt = 0; nt < 4; nt++) {
                oacc[nt][0] *= a0; oacc[nt][1] *= a0;
                oacc[nt][2] *= a1; oacc[nt][3] *= a1;
            }
            uint32_t ph4[2][4], pl4[2][4];
#pragma unroll
            for (int ks = 0; ks < 2; ks++) {
                uint32_t ad = sb + 48384 + (arow*40 + ks*16 + ac)*2;
                LDSM_X4(ph4[ks], ad);
                LDSM_X4(pl4[ks], ad + 1280);
            }
#pragma unroll
            for (int nt = 0; nt < 4; nt++) {
                int n0 = w*32 + nt*8;
#pragma unroll
                for (int ks = 0; ks < 2; ks++) {
                    uint32_t bd = buf + ((ks*16 + (lane & 15))*584 + n0)*2;
                    uint32_t vh[2], vl[2];
                    LDSM_X2T(vh, bd);
                    LDSM_X2T(vl, bd + AT_LO);
                    mma16816(oacc[nt], ph4[ks], vh);
                    mma16816(oacc[nt], ph4[ks], vl);
                    mma16816(oacc[nt], pl4[ks], vh);
                }
            }
        }
        __syncthreads();
    }

    {
        int m_ = lane >> 2, e0 = 2*(lane & 3);
        float li0 = 1.f / l_s[m_];
        float li1 = 1.f / l_s[m_ + 8];
#pragma unroll
        for (int nt = 0; nt < 4; nt++) {
            int c0 = w*32 + nt*8 + e0;
            *(float2*)(omid + (long)bs*8192 + m_*512 + c0)     = make_float2(oacc[nt][0]*li0, oacc[nt][1]*li0);
            *(float2*)(omid + (long)bs*8192 + (m_+8)*512 + c0) = make_float2(oacc[nt][2]*li1, oacc[nt][3]*li1);
        }
    }
}

// ---------------- host orchestration -------------------------------------------
extern "C" void kernel_launch(void* const* d_in, const int* in_sizes, int n_in,
                              void* d_out, int out_size) {
    const float* x      = (const float*)d_in[0];
    const float* fcos   = (const float*)d_in[1];
    const float* fsin   = (const float*)d_in[2];
    const float* wq_a   = (const float*)d_in[4];
    const float* qnw    = (const float*)d_in[5];
    const float* wq_b   = (const float*)d_in[6];
    const float* wkv_a  = (const float*)d_in[7];
    const float* kvnw   = (const float*)d_in[8];
    const float* wkv_b  = (const float*)d_in[9];
    const float* wo     = (const float*)d_in[10];
    const float* iwqb   = (const float*)d_in[11];
    const float* iwk    = (const float*)d_in[12];
    const float* iknw   = (const float*)d_in[13];
    const float* iknb   = (const float*)d_in[14];
    const float* iwp    = (const float*)d_in[15];
    float* out = (float*)d_out;

    float *qr, *q, *kvfull, *kv, *kpe, *qabs, *qi, *ki, *wts, *iscore, *omid, *o2, *wt;
    __nv_bfloat16 *khi, *klo;
    int* topkb;
    cudaGetSymbolAddress((void**)&qr,     g_qr);
    cudaGetSymbolAddress((void**)&q,      g_q);
    cudaGetSymbolAddress((void**)&kvfull, g_kvfull);
    cudaGetSymbolAddress((void**)&kv,     g_kv);
    cudaGetSymbolAddress((void**)&kpe,    g_kpe);
    cudaGetSymbolAddress((void**)&qabs,   g_qabs);
    cudaGetSymbolAddress((void**)&qi,     g_qi);
    cudaGetSymbolAddress((void**)&ki,     g_ki);
    cudaGetSymbolAddress((void**)&wts,    g_wts);
    cudaGetSymbolAddress((void**)&iscore, g_iscore);
    cudaGetSymbolAddress((void**)&topkb,  g_topk);
    cudaGetSymbolAddress((void**)&omid,   g_omid);
    cudaGetSymbolAddress((void**)&o2,     g_o2);
    cudaGetSymbolAddress((void**)&wt,     g_wkvbT);
    cudaGetSymbolAddress((void**)&khi,    g_khi);
    cudaGetSymbolAddress((void**)&klo,    g_klo);

    cudaFuncSetAttribute(gemm_mma, cudaFuncAttributeMaxDynamicSharedMemorySize, GM_SMEM);
    cudaFuncSetAttribute(attn_tc,  cudaFuncAttributeMaxDynamicSharedMemorySize, AT_SMEM);

    static cudaStream_t s1 = 0, s2 = 0;
    static cudaEvent_t eF = 0, eQR = 0, eWT = 0, eT0 = 0, eT1 = 0, eQI1 = 0;
    if (s1 == 0) {
        cudaStreamCreateWithFlags(&s1, cudaStreamNonBlocking);
        cudaStreamCreateWithFlags(&s2, cudaStreamNonBlocking);
        cudaEventCreateWithFlags(&eF,   cudaEventDisableTiming);
        cudaEventCreateWithFlags(&eQR,  cudaEventDisableTiming);
        cudaEventCreateWithFlags(&eWT,  cudaEventDisableTiming);
        cudaEventCreateWithFlags(&eT0,  cudaEventDisableTiming);
        cudaEventCreateWithFlags(&eT1,  cudaEventDisableTiming);
        cudaEventCreateWithFlags(&eQI1, cudaEventDisableTiming);
    }
    cudaStream_t s0 = 0;

    cudaEventRecord(eF, s0);
    cudaStreamWaitEvent(s1, eF, 0);
    cudaStreamWaitEvent(s2, eF, 0);

    // ---- s0: qr chain
    gemm_bt<<<dim3(6, 32, 1), 256, 0, s0>>>(x, 2048, 0, wq_a, 2048, 0, qr, 768, 0, 4096, 768, 2048);
    rmsnorm_kernel<<<4096, 256, 0, s0>>>(qr, qnw, 768);
    cudaEventRecord(eQR, s0);

    // ---- s2: kv path + weight transpose, then qi(b1) chain
    gemm_mma<<<dim3(5, 32, 1), 256, GM_SMEM, s2>>>(x, 2048, 0, wkv_a, 2048, 0, kvfull, 576, 0, 4096, 576, 2048);
    kvpost_kernel<<<4096, 256, 0, s2>>>(kvfull, kvnw, fcos, fsin, kv, kpe);
    kvsplit_kernel<<<(BS_*576 + 255)/256, 256, 0, s2>>>(kv, kpe, khi, klo);
    transpose_wkvb<<<(16*128*512 + 255)/256, 256, 0, s2>>>(wkv_b, wt);
    cudaEventRecord(eWT, s2);
    cudaStreamWaitEvent(s2, eQR, 0);
    gemm_bt<<<dim3(16, 16, 1), 256, 0, s2>>>(qr + (long)S_*768, 768, 0, iwqb, 768, 0,
                                             qi + (long)S_*2048, 2048, 0, 2048, 2048, 768);
    rope_qi_kernel<<<(S_*16*32 + 255)/256, 256, 0, s2>>>(qi + (long)S_*2048, fcos, fsin, S_);
    cudaEventRecord(eQI1, s2);

    // ---- s1: indexer path: ki/wts, then qi(b0) -> iscore(b0) -> topk(b0),
    //      then iscore(b1)/topk(b1) (qi(b1) from s2)
    gemm_bt<<<dim3(1, 32, 1), 256, 0, s1>>>(x, 2048, 0, iwk, 2048, 0, ki, 128, 0, 4096, 128, 2048);
    kipost_kernel<<<4096, 128, 0, s1>>>(ki, iknw, iknb, fcos, fsin);
    gemm_bt<<<dim3(1, 32, 1), 256, 0, s1>>>(x, 2048, 0, iwp, 2048, 0, wts, 16, 0, 4096, 16, 2048);
    cudaStreamWaitEvent(s1, eQR, 0);
    gemm_bt<<<dim3(16, 16, 1), 256, 0, s1>>>(qr, 768, 0, iwqb, 768, 0, qi, 2048, 0, 2048, 2048, 768);
    rope_qi_kernel<<<(S_*16*32 + 255)/256, 256, 0, s1>>>(qi, fcos, fsin, S_);
    iscore_kernel<<<dim3(32, 12, 1), 256, 0, s1>>>(qi, ki, wts, iscore, 512);
    topk_kernel<<<1536, 256, 0, s1>>>(iscore, topkb, 512);
    cudaEventRecord(eT0, s1);
    cudaStreamWaitEvent(s1, eQI1, 0);
    iscore_kernel<<<dim3(32, 12, 1), 256, 0, s1>>>(qi + (long)S_*2048, ki + (long)S_*128,
                                                   wts + (long)S_*16, iscore + (long)S_*S_, 512);
    topk_kernel<<<1536, 256, 0, s1>>>(iscore + (long)S_*S_, topkb + (long)S_*ITOPK_, 512);
    cudaEventRecord(eT1, s1);

    // ---- s0 continues: q chain, qabs, early attention (s<512, both batches),
    //      then main attention per batch + output tail
    gemm_mma<<<dim3(24, 32, 1), 256, GM_SMEM, s0>>>(qr, 768, 0, wq_b, 768, 0, q, 3072, 0, 4096, 3072, 768);
    rope_q_kernel<<<(BS_*16*32 + 255)/256, 256, 0, s0>>>(q, fcos, fsin);
    cudaStreamWaitEvent(s0, eWT, 0);
    gemm_mma<<<dim3(4, 32, 16), 256, GM_SMEM, s0>>>(q, 3072, 192, wt, 128, 65536, qabs, 8192, 512,
                                                    4096, 512, 128);
    attn_tc<<<dim3(512, 2, 1), 512, AT_SMEM, s0>>>(qabs, q, khi, klo, topkb, omid, 0, 0);
    cudaStreamWaitEvent(s0, eT0, 0);
    attn_tc<<<dim3(1536, 1, 1), 512, AT_SMEM, s0>>>(qabs, q, khi, klo, topkb, omid, 0, 512);
    cudaStreamWaitEvent(s0, eT1, 0);
    attn_tc<<<dim3(1536, 1, 1), 512, AT_SMEM, s0>>>(qabs, q, khi, klo, topkb, omid, 1, 512);
    gemm_mma<<<dim3(1, 32, 16), 256, GM_SMEM, s0>>>(omid, 8192, 512, wkv_b + 128*512, 512, 256*512,
                                                    o2, 2048, 128, 4096, 128, 512);
    gemm_mma<<<dim3(16, 32, 1), 256, GM_SMEM, s0>>>(o2, 2048, 0, wo, 2048, 0, out, 2048, 0, 4096, 2048, 2048);
}

// round 15
// speedup vs baseline: 1.0489x; 1.0489x over previous
#include <cuda_runtime.h>
#include <cuda_bf16.h>
#include <math.h>
#include <stdint.h>

// Problem constants
#define B_    2
#define S_    2048
#define DIM_  2048
#define NH_   16
#define QLR_  768
#define KVLR_ 512
#define NOPE_ 128
#define ROPE_ 64
#define VDIM_ 128
#define IH_   16
#define IHD_  128
#define ITOPK_ 512
#define BS_   (B_*S_)   // 4096

// ---------------- scratch (device globals; no allocation allowed) -------------
__device__ float g_qr[BS_*QLR_];
__device__ float g_q[BS_*NH_*(NOPE_+ROPE_)];
__device__ float g_kvfull[BS_*(KVLR_+ROPE_)];
__device__ float g_kv[BS_*KVLR_];
__device__ float g_kpe[BS_*ROPE_];
__device__ float g_qabs[BS_*NH_*KVLR_];
__device__ float g_qi[BS_*IH_*IHD_];
__device__ float g_ki[BS_*IHD_];
__device__ float g_wts[BS_*IH_];
__device__ float g_iscore[B_*S_*S_];
__device__ int   g_topk[BS_*ITOPK_];
__device__ float g_omid[BS_*NH_*KVLR_];
__device__ float g_o2[BS_*NH_*VDIM_];
__device__ float g_wkvbT[16*512*128];            // transposed wkv_b[:, :128, :] -> [h][c][d]
__device__ __nv_bfloat16 g_khi[BS_*576];         // kv||kpe hi split
__device__ __nv_bfloat16 g_klo[BS_*576];         // kv||kpe lo split

// =================== helpers ==================================================
__device__ __forceinline__ uint32_t smem_u32(const void* p) {
    uint32_t a;
    asm("{ .reg .u64 t; cvta.to.shared.u64 t, %1; cvt.u32.u64 %0, t; }" : "=r"(a) : "l"(p));
    return a;
}
__device__ __forceinline__ uint32_t pack_hi(float x, float y) {
    __nv_bfloat162 p;
    p.x = __float2bfloat16_rn(x);
    p.y = __float2bfloat16_rn(y);
    return *(uint32_t*)&p;
}
__device__ __forceinline__ uint32_t pack_lo(float x, float y) {
    __nv_bfloat16 hx = __float2bfloat16_rn(x);
    __nv_bfloat16 hy = __float2bfloat16_rn(y);
    __nv_bfloat162 p;
    p.x = __float2bfloat16_rn(x - __bfloat162float(hx));
    p.y = __float2bfloat16_rn(y - __bfloat162float(hy));
    return *(uint32_t*)&p;
}
__device__ __forceinline__ void mma16816(float* c, const uint32_t* a, const uint32_t* b) {
    asm volatile("mma.sync.aligned.m16n8k16.row.col.f32.bf16.bf16.f32 "
        "{%0,%1,%2,%3}, {%4,%5,%6,%7}, {%8,%9}, {%0,%1,%2,%3};"
        : "+f"(c[0]), "+f"(c[1]), "+f"(c[2]), "+f"(c[3])
        : "r"(a[0]), "r"(a[1]), "r"(a[2]), "r"(a[3]), "r"(b[0]), "r"(b[1]));
}
#define LDSM_X4(r, a) asm volatile("ldmatrix.sync.aligned.m8n8.x4.shared.b16 {%0,%1,%2,%3}, [%4];" \
    : "=r"((r)[0]),"=r"((r)[1]),"=r"((r)[2]),"=r"((r)[3]) : "r"(a))
#define LDSM_X2(r, a) asm volatile("ldmatrix.sync.aligned.m8n8.x2.shared.b16 {%0,%1}, [%2];" \
    : "=r"((r)[0]),"=r"((r)[1]) : "r"(a))
#define LDSM_X2T(r, a) asm volatile("ldmatrix.sync.aligned.m8n8.x2.trans.shared.b16 {%0,%1}, [%2];" \
    : "=r"((r)[0]),"=r"((r)[1]) : "r"(a))
#define CP_ASYNC16(dst, src) asm volatile("cp.async.cg.shared.global [%0], [%1], 16;" :: "r"(dst), "l"(src))
#define CP_COMMIT() asm volatile("cp.async.commit_group;" ::: "memory")
#define CP_WAIT(n)  asm volatile("cp.async.wait_group %0;" :: "n"(n) : "memory")

// word-granularity swizzled smem address for gemm_mma tiles (128 rows x 16 words)
__device__ __forceinline__ int sw_addr(int row, int w) {
    return row*16 + (w ^ ((((row)>>1)&3)<<2));
}

// =================== tensor-core GEMM (bf16x3): C[M,N]=A[M,K]@B[N,K]^T ========
#define GM_SMEM 65536

__global__ void __launch_bounds__(256, 1)
gemm_mma(const float* __restrict__ A, int lda, long aZ,
         const float* __restrict__ Bm, int ldb, long bZ,
         float* __restrict__ C, int ldc, long cZ,
         int M, int N, int K) {
    extern __shared__ uint32_t smw[];
    A  += (long)blockIdx.z * aZ;
    Bm += (long)blockIdx.z * bZ;
    C  += (long)blockIdx.z * cZ;
    int m0 = blockIdx.y * 128, n0 = blockIdx.x * 128;
    int tid = threadIdx.x, lane = tid & 31, wid = tid >> 5;
    int wm = wid >> 2, wn = wid & 3;
    int g = lane >> 2, tig = lane & 3;

    float acc[4][4][4];
#pragma unroll
    for (int i = 0; i < 4; i++)
#pragma unroll
        for (int j = 0; j < 4; j++)
#pragma unroll
            for (int r = 0; r < 4; r++) acc[i][j][r] = 0.f;

    int arow = tid >> 1, acol = (tid & 1) * 16;
    int nch = K >> 5;

    float4 ra[4], rb[4];
    {
        const float* ap = A + (long)(m0 + arow)*lda + acol;
        bool aok = (m0 + arow) < M;
#pragma unroll
        for (int i = 0; i < 4; i++)
            ra[i] = aok ? *(const float4*)(ap + i*4) : make_float4(0.f,0.f,0.f,0.f);
        const float* bp = Bm + (long)(n0 + arow)*ldb + acol;
        bool bok = (n0 + arow) < N;
#pragma unroll
        for (int i = 0; i < 4; i++)
            rb[i] = bok ? *(const float4*)(bp + i*4) : make_float4(0.f,0.f,0.f,0.f);
    }

    for (int it = 0; it < nch; it++) {
        int stg = it & 1;
        uint32_t* sAhi = smw + stg*8192;
        uint32_t* sAlo = sAhi + 2048;
        uint32_t* sBhi = sAhi + 4096;
        uint32_t* sBlo = sAhi + 6144;
        {
            uint32_t hw[8], lw[8];
#pragma unroll
            for (int i = 0; i < 4; i++) {
                hw[i*2]   = pack_hi(ra[i].x, ra[i].y);
                hw[i*2+1] = pack_hi(ra[i].z, ra[i].w);
                lw[i*2]   = pack_lo(ra[i].x, ra[i].y);
                lw[i*2+1] = pack_lo(ra[i].z, ra[i].w);
            }
            int g0 = (((tid&1)*2 + 0) ^ ((arow>>1)&3)) * 4;
            int g1 = (((tid&1)*2 + 1) ^ ((arow>>1)&3)) * 4;
            uint32_t* dst = sAhi + arow*16;
            *(uint4*)(dst + g0) = make_uint4(hw[0],hw[1],hw[2],hw[3]);
            *(uint4*)(dst + g1) = make_uint4(hw[4],hw[5],hw[6],hw[7]);
            dst = sAlo + arow*16;
            *(uint4*)(dst + g0) = make_uint4(lw[0],lw[1],lw[2],lw[3]);
            *(uint4*)(dst + g1) = make_uint4(lw[4],lw[5],lw[6],lw[7]);
#pragma unroll
            for (int i = 0; i < 4; i++) {
                hw[i*2]   = pack_hi(rb[i].x, rb[i].y);
                hw[i*2+1] = pack_hi(rb[i].z, rb[i].w);
                lw[i*2]   = pack_lo(rb[i].x, rb[i].y);
                lw[i*2+1] = pack_lo(rb[i].z, rb[i].w);
            }
            dst = sBhi + arow*16;
            *(uint4*)(dst + g0) = make_uint4(hw[0],hw[1],hw[2],hw[3]);
            *(uint4*)(dst + g1) = make_uint4(hw[4],hw[5],hw[6],hw[7]);
            dst = sBlo + arow*16;
            *(uint4*)(dst + g0) = make_uint4(lw[0],lw[1],lw[2],lw[3]);
            *(uint4*)(dst + g1) = make_uint4(lw[4],lw[5],lw[6],lw[7]);
        }
        __syncthreads();
        if (it + 1 < nch) {
            int gk = (it + 1) << 5;
            const float* ap = A + (long)(m0 + arow)*lda + gk + acol;
            bool aok = (m0 + arow) < M;
#pragma unroll
            for (int i = 0; i < 4; i++)
                ra[i] = aok ? *(const float4*)(ap + i*4) : make_float4(0.f,0.f,0.f,0.f);
            const float* bp = Bm + (long)(n0 + arow)*ldb + gk + acol;
            bool bok = (n0 + arow) < N;
#pragma unroll
            for (int i = 0; i < 4; i++)
                rb[i] = bok ? *(const float4*)(bp + i*4) : make_float4(0.f,0.f,0.f,0.f);
        }
#pragma unroll
        for (int ks = 0; ks < 2; ks++) {
            uint32_t bh[4][2], bl[4][2];
#pragma unroll
            for (int nt = 0; nt < 4; nt++) {
                int nrow = wn*32 + nt*8 + g;
                int w0 = ks*8 + tig;
                bh[nt][0] = sBhi[sw_addr(nrow, w0)];
                bh[nt][1] = sBhi[sw_addr(nrow, w0+4)];
                bl[nt][0] = sBlo[sw_addr(nrow, w0)];
                bl[nt][1] = sBlo[sw_addr(nrow, w0+4)];
            }
#pragma unroll
            for (int mt = 0; mt < 4; mt++) {
                int ar = wm*64 + mt*16 + g;
                int w0 = ks*8 + tig;
                uint32_t ah[4], al[4];
                ah[0] = sAhi[sw_addr(ar,   w0)];
                ah[1] = sAhi[sw_addr(ar+8, w0)];
                ah[2] = sAhi[sw_addr(ar,   w0+4)];
                ah[3] = sAhi[sw_addr(ar+8, w0+4)];
                al[0] = sAlo[sw_addr(ar,   w0)];
                al[1] = sAlo[sw_addr(ar+8, w0)];
                al[2] = sAlo[sw_addr(ar,   w0+4)];
                al[3] = sAlo[sw_addr(ar+8, w0+4)];
#pragma unroll
                for (int nt = 0; nt < 4; nt++) {
                    mma16816(acc[mt][nt], ah, bh[nt]);
                    mma16816(acc[mt][nt], ah, bl[nt]);
                    mma16816(acc[mt][nt], al, bh[nt]);
                }
            }
        }
        __syncthreads();
    }
#pragma unroll
    for (int mt = 0; mt < 4; mt++) {
#pragma unroll
        for (int nt = 0; nt < 4; nt++) {
            int r0 = m0 + wm*64 + mt*16 + g;
            int c0 = n0 + wn*32 + nt*8 + tig*2;
            if (c0 < N) {
                if (r0 < M)
                    *(float2*)(C + (long)r0*ldc + c0) = make_float2(acc[mt][nt][0], acc[mt][nt][1]);
                if (r0 + 8 < M)
                    *(float2*)(C + (long)(r0+8)*ldc + c0) = make_float2(acc[mt][nt][2], acc[mt][nt][3]);
            }
        }
    }
}

// transpose wkv_b[:, :128, :] -> wt[h][c][d]
__global__ void transpose_wkvb(const float* __restrict__ w, float* __restrict__ wt) {
    int idx = blockIdx.x * 256 + threadIdx.x;
    if (idx >= 16*128*512) return;
    int c = idx & 511, d = (idx >> 9) & 127, h = idx >> 16;
    wt[h*65536 + c*128 + d] = w[h*131072 + d*512 + c];
}

// ---------------- fp32 GEMM (bit-exact k-order, float4 loads) ------------------
__global__ void __launch_bounds__(256)
gemm_bt(const float* __restrict__ A, int lda, long aZ,
        const float* __restrict__ Bm, int ldb, long bZ,
        float* __restrict__ C, int ldc, long cZ,
        int M, int N, int K) {
    A  += (long)blockIdx.z * aZ;
    Bm += (long)blockIdx.z * bZ;
    C  += (long)blockIdx.z * cZ;
    int n0 = blockIdx.x * 128, m0 = blockIdx.y * 128;
    __shared__ float As[16][129];
    __shared__ float Bs[16][129];
    int tid = threadIdx.x;
    int tx = tid & 15, ty = tid >> 4;
    int lq = tid & 3, lm = tid >> 2;     // float4 load indices: k-quad, row
    float acc[8][8];
#pragma unroll
    for (int i = 0; i < 8; i++)
#pragma unroll
        for (int j = 0; j < 8; j++) acc[i][j] = 0.f;

    for (int k0 = 0; k0 < K; k0 += 16) {
#pragma unroll
        for (int p = 0; p < 2; p++) {
            int m = lm + 64*p;
            float4 va = *(const float4*)(A + (long)(m0 + m)*lda + k0 + lq*4);
            As[lq*4+0][m] = va.x; As[lq*4+1][m] = va.y;
            As[lq*4+2][m] = va.z; As[lq*4+3][m] = va.w;
            int gn = n0 + m;
            float4 vb = (gn < N) ? *(const float4*)(Bm + (long)gn*ldb + k0 + lq*4)
                                 : make_float4(0.f,0.f,0.f,0.f);
            Bs[lq*4+0][m] = vb.x; Bs[lq*4+1][m] = vb.y;
            Bs[lq*4+2][m] = vb.z; Bs[lq*4+3][m] = vb.w;
        }
        __syncthreads();
#pragma unroll
        for (int kk = 0; kk < 16; kk++) {
            float a[8], bb[8];
#pragma unroll
            for (int i = 0; i < 8; i++) a[i]  = As[kk][ty + 16*i];
#pragma unroll
            for (int j = 0; j < 8; j++) bb[j] = Bs[kk][tx + 16*j];
#pragma unroll
            for (int i = 0; i < 8; i++)
#pragma unroll
                for (int j = 0; j < 8; j++) acc[i][j] += a[i]*bb[j];
        }
        __syncthreads();
    }
#pragma unroll
    for (int i = 0; i < 8; i++)
#pragma unroll
        for (int j = 0; j < 8; j++) {
            int gm = m0 + ty + 16*i, gn = n0 + tx + 16*j;
            if (gm < M && gn < N) C[(long)gm*ldc + gn] = acc[i][j];
        }
}

// ---------------- elementwise / norm / rope -----------------------------------
__global__ void rmsnorm_kernel(float* __restrict__ x, const float* __restrict__ w, int L) {
    int row = blockIdx.x, tid = threadIdx.x;
    float* pr = x + (long)row * L;
    float ss = 0.f;
    for (int i = tid; i < L; i += 256) { float v = pr[i]; ss += v*v; }
    __shared__ float red[256];
    red[tid] = ss; __syncthreads();
    for (int o = 128; o > 0; o >>= 1) { if (tid < o) red[tid] += red[tid+o]; __syncthreads(); }
    float inv = rsqrtf(red[0] / (float)L + 1e-6f);
    for (int i = tid; i < L; i += 256) pr[i] = w[i] * pr[i] * inv;
}

__global__ void kvpost_kernel(const float* __restrict__ kvfull, const float* __restrict__ w,
                              const float* __restrict__ fcos, const float* __restrict__ fsin,
                              float* __restrict__ kv, float* __restrict__ kpe) {
    int row = blockIdx.x, s = row & (S_-1), tid = threadIdx.x;
    const float* src = kvfull + (long)row * 576;
    float ss = 0.f;
    for (int i = tid; i < 512; i += 256) { float v = src[i]; ss += v*v; }
    __shared__ float red[256];
    red[tid] = ss; __syncthreads();
    for (int o = 128; o > 0; o >>= 1) { if (tid < o) red[tid] += red[tid+o]; __syncthreads(); }
    float inv = rsqrtf(red[0] / 512.f + 1e-6f);
    for (int i = tid; i < 512; i += 256) kv[(long)row*512 + i] = w[i] * src[i] * inv;
    if (tid < 32) {
        float x1 = src[512 + tid], x2 = src[544 + tid];
        float c = fcos[s*32 + tid], sn = fsin[s*32 + tid];
        kpe[(long)row*64 + tid]      = x1*c - x2*sn;
        kpe[(long)row*64 + 32 + tid] = x1*sn + x2*c;
    }
}

// split kv||kpe into bf16 hi/lo global arrays
__global__ void kvsplit_kernel(const float* __restrict__ kv, const float* __restrict__ kpe,
                               __nv_bfloat16* __restrict__ khi, __nv_bfloat16* __restrict__ klo) {
    int idx = blockIdx.x*256 + threadIdx.x;
    if (idx >= BS_*576) return;
    int r = idx / 576, d = idx - r*576;
    float v = (d < 512) ? kv[(long)r*512 + d] : kpe[(long)r*64 + d - 512];
    __nv_bfloat16 hi = __float2bfloat16_rn(v);
    khi[idx] = hi;
    klo[idx] = __float2bfloat16_rn(v - __bfloat162float(hi));
}

__global__ void kipost_kernel(float* __restrict__ ki, const float* __restrict__ w,
                              const float* __restrict__ bvec,
                              const float* __restrict__ fcos, const float* __restrict__ fsin) {
    int row = blockIdx.x, s = row & (S_-1), tid = threadIdx.x; // 128 threads
    float* pr = ki + (long)row * 128;
    float v = pr[tid];
    __shared__ float red[128];
    red[tid] = v; __syncthreads();
    for (int o = 64; o > 0; o >>= 1) { if (tid < o) red[tid] += red[tid+o]; __syncthreads(); }
    float mean = red[0] / 128.f;
    __syncthreads();
    float d = v - mean;
    red[tid] = d*d; __syncthreads();
    for (int o = 64; o > 0; o >>= 1) { if (tid < o) red[tid] += red[tid+o]; __syncthreads(); }
    float var = red[0] / 128.f;
    __syncthreads();
    float y = d * rsqrtf(var + 1e-6f) * w[tid] + bvec[tid];
    __shared__ float yb[128];
    yb[tid] = y; __syncthreads();
    float outv;
    if (tid < 32) {
        float c = fcos[s*32 + tid], sn = fsin[s*32 + tid];
        outv = yb[tid]*c - yb[tid+32]*sn;
    } else if (tid < 64) {
        int i = tid - 32;
        float c = fcos[s*32 + i], sn = fsin[s*32 + i];
        outv = yb[i]*sn + yb[tid]*c;
    } else {
        outv = y;
    }
    pr[tid] = outv;
}

__global__ void rope_q_kernel(float* __restrict__ q, const float* __restrict__ fcos,
                              const float* __restrict__ fsin) {
    int idx = blockIdx.x * blockDim.x + threadIdx.x;
    if (idx >= BS_*16*32) return;
    int i = idx & 31, h = (idx >> 5) & 15, bs = idx >> 9;
    int s = bs & (S_-1);
    long base = (long)bs*3072 + h*192 + 128;
    float x1 = q[base + i], x2 = q[base + 32 + i];
    float c = fcos[s*32 + i], sn = fsin[s*32 + i];
    q[base + i]      = x1*c - x2*sn;
    q[base + 32 + i] = x1*sn + x2*c;
}

__global__ void rope_qi_kernel(float* __restrict__ qi, const float* __restrict__ fcos,
                               const float* __restrict__ fsin) {
    int idx = blockIdx.x * blockDim.x + threadIdx.x;
    if (idx >= BS_*16*32) return;
    int i = idx & 31, h = (idx >> 5) & 15, bs = idx >> 9;
    int s = bs & (S_-1);
    long base = (long)bs*2048 + h*128;
    float x1 = qi[base + i], x2 = qi[base + 32 + i];
    float c = fcos[s*32 + i], sn = fsin[s*32 + i];
    qi[base + i]      = x1*c - x2*sn;
    qi[base + 32 + i] = x1*sn + x2*c;
}

// ---------------- indexer score (128s x 64t tile, 2 heads/pass, bit-exact) ----
// Rows start at s_base (rows s<512 are never read downstream and are skipped).
__global__ void __launch_bounds__(256)
iscore_kernel(const float* __restrict__ qi, const float* __restrict__ ki,
              const float* __restrict__ wts, float* __restrict__ iscore, int s_base) {
    int s0 = s_base + blockIdx.y * 128, t0 = blockIdx.x * 64;
    int tid = threadIdx.x;
    if (t0 > s0 + 127) return;   // fully-masked tile: never read downstream
    int tx = tid & 15, ty = tid >> 4;
    int lq = tid & 3, lm = tid >> 2;
    __shared__ float qs[2][16][129];
    __shared__ float ks[16][65];
    __shared__ float ws_s[16][128];
    const float IW_SCALE = rsqrtf(2048.0f);
    for (int i = tid; i < 16*128; i += 256) {
        int m = i >> 4, h = i & 15;
        ws_s[h][m] = wts[((long)(s0 + m))*16 + h] * IW_SCALE;
    }
    float acc[8][4];
#pragma unroll
    for (int i = 0; i < 8; i++)
#pragma unroll
        for (int j = 0; j < 4; j++) acc[i][j] = 0.f;
    __syncthreads();

    for (int h = 0; h < 16; h += 2) {
        float dot[2][8][4];
#pragma unroll
        for (int e = 0; e < 2; e++)
#pragma unroll
            for (int i = 0; i < 8; i++)
#pragma unroll
                for (int j = 0; j < 4; j++) dot[e][i][j] = 0.f;
        for (int d0 = 0; d0 < 128; d0 += 16) {
#pragma unroll
            for (int e = 0; e < 2; e++)
#pragma unroll
                for (int p = 0; p < 2; p++) {
                    int m = lm + 64*p;
                    float4 v = *(const float4*)(qi + ((long)(s0 + m))*2048 + (h+e)*128 + d0 + lq*4);
                    qs[e][lq*4+0][m] = v.x; qs[e][lq*4+1][m] = v.y;
                    qs[e][lq*4+2][m] = v.z; qs[e][lq*4+3][m] = v.w;
                }
            {
                float4 v = *(const float4*)(ki + ((long)(t0 + lm))*128 + d0 + lq*4);
                ks[lq*4+0][lm] = v.x; ks[lq*4+1][lm] = v.y;
                ks[lq*4+2][lm] = v.z; ks[lq*4+3][lm] = v.w;
            }
            __syncthreads();
#pragma unroll
            for (int kk = 0; kk < 16; kk++) {
                float a0[8], a1[8], bb[4];
#pragma unroll
                for (int i = 0; i < 8; i++) { a0[i] = qs[0][kk][ty + 16*i]; a1[i] = qs[1][kk][ty + 16*i]; }
#pragma unroll
                for (int j = 0; j < 4; j++) bb[j] = ks[kk][tx + 16*j];
#pragma unroll
                for (int i = 0; i < 8; i++)
#pragma unroll
                    for (int j = 0; j < 4; j++) {
                        dot[0][i][j] += a0[i]*bb[j];
                        dot[1][i][j] += a1[i]*bb[j];
                    }
            }
            __syncthreads();
        }
#pragma unroll
        for (int e = 0; e < 2; e++)
#pragma unroll
            for (int i = 0; i < 8; i++) {
                float w = ws_s[h+e][ty + 16*i];
#pragma unroll
                for (int j = 0; j < 4; j++) acc[i][j] += fmaxf(dot[e][i][j], 0.f) * w;
            }
    }
#pragma unroll
    for (int i = 0; i < 8; i++)
#pragma unroll
        for (int j = 0; j < 4; j++) {
            int s = s0 + ty + 16*i, t = t0 + tx + 16*j;
            float mval = (t <= s) ? 0.f : -1000000000.0f;
            iscore[((long)s)*S_ + t] = acc[i][j] + mval;
        }
}

// ---------------- exact top-512 per row (prefix-only radix, deterministic) ----
// Launched only for rows s >= 512 (s = blockIdx.x + s_off).
__global__ void topk_kernel(const float* __restrict__ iscore, int* __restrict__ out, int s_off) {
    int s = blockIdx.x + s_off;
    int tid = threadIdx.x; // 256
    int* o = out + (long)s * ITOPK_;
    const float* p = iscore + (long)s * S_;
    __shared__ unsigned int hist[256];
    __shared__ unsigned int s_prefix;
    __shared__ int s_rem;
    __shared__ int sgt[257], seq[257];
    if (tid == 0) { s_prefix = 0u; s_rem = ITOPK_; }
    __syncthreads();
    for (int pass = 0; pass < 4; pass++) {
        hist[tid] = 0u;
        __syncthreads();
        int shift = 24 - 8*pass;
        unsigned int pref = s_prefix;
        for (int e = 0; e < 8; e++) {
            int j = tid*8 + e;
            if (j > s) break;
            unsigned int u = __float_as_uint(p[j]);
            unsigned int k = (u & 0x80000000u) ? ~u : (u | 0x80000000u);
            bool ok = (pass == 0) || (((k ^ pref) >> (shift + 8)) == 0u);
            if (ok) atomicAdd(&hist[(k >> shift) & 255u], 1u);
        }
        __syncthreads();
        if (tid == 0) {
            int rem = s_rem;
            unsigned int cum = 0; int bin = 0;
            for (int bb = 255; bb >= 0; bb--) {
                if (cum + hist[bb] >= (unsigned)rem) { bin = bb; break; }
                cum += hist[bb];
            }
            s_rem = rem - (int)cum;
            s_prefix = s_prefix | ((unsigned)bin << shift);
        }
        __syncthreads();
    }
    unsigned int kth = s_prefix;
    int cgt = 0, ceq = 0;
    for (int e = 0; e < 8; e++) {
        int j = tid*8 + e;
        if (j > s) break;
        unsigned int u = __float_as_uint(p[j]);
        unsigned int k = (u & 0x80000000u) ? ~u : (u | 0x80000000u);
        cgt += (k > kth); ceq += (k == kth);
    }
    sgt[tid] = cgt; seq[tid] = ceq;
    __syncthreads();
    if (tid == 0) {
        int ag = 0, ae = 0;
        for (int i = 0; i < 256; i++) {
            int tg = sgt[i], te = seq[i];
            sgt[i] = ag; seq[i] = ae;
            ag += tg; ae += te;
        }
        sgt[256] = ag;
    }
    __syncthreads();
    int total_gt = sgt[256];
    int pgt = sgt[tid];
    int peq = total_gt + seq[tid];
    for (int e = 0; e < 8; e++) {
        int j = tid*8 + e;
        if (j > s) break;
        unsigned int u = __float_as_uint(p[j]);
        unsigned int k = (u & 0x80000000u) ? ~u : (u | 0x80000000u);
        if (k > kth) { o[pgt++] = j; }
        else if (k == kth) { if (peq < ITOPK_) o[peq] = j; peq++; }
    }
}

// ---------------- fused flash-style tensor-core sparse attention ---------------
// 512 threads / 16 warps, Q hi-fragments hoisted, all-invalid chunks skipped.
// Rows s<512 synthesize tl[j]=j (identical to topk output) -> no topk dependency.
#define AT_SMEM 200448
#define AT_BUF0 50944
#define AT_BUFSZ 74752
#define AT_LO 37376

__device__ __forceinline__ void at_gather(const __nv_bfloat16* __restrict__ khi,
                                          const __nv_bfloat16* __restrict__ klo,
                                          long kb, const int* tl, int c,
                                          uint32_t bufaddr, int tid) {
    int jloc = tid >> 4, sg0 = tid & 15;   // 32 rows x 16 threads
    int t = tl[c*32 + jloc];
    const char* sh = (const char*)(khi + kb + (long)t*576);
    const char* sl = (const char*)(klo + kb + (long)t*576);
    uint32_t dh = bufaddr + jloc*1168;
#pragma unroll
    for (int u = 0; u < 9; u++) {
        int ch = sg0 + u*16;               // 0..143: 72 hi chunks then 72 lo
        if (ch < 72) CP_ASYNC16(dh + ch*16, sh + ch*16);
        else         CP_ASYNC16(dh + AT_LO + (ch-72)*16, sl + (ch-72)*16);
    }
    CP_COMMIT();
}

__global__ void __launch_bounds__(512, 1)
attn_tc(const float* __restrict__ qabs, const float* __restrict__ qfull,
        const __nv_bfloat16* __restrict__ khi, const __nv_bfloat16* __restrict__ klo,
        const int* __restrict__ topk, float* __restrict__ omid, int b0, int s_off) {
    extern __shared__ char sm[];
    uint32_t sb = smem_u32(sm);
    int* tl = (int*)sm;
    float* m_s  = (float*)(sm + 2048);
    float* l_s  = (float*)(sm + 2112);
    float* al_s = (float*)(sm + 2176);
    float* sc   = (float*)(sm + 2304);       // [4][16][34]
    __nv_bfloat16* qh = (__nv_bfloat16*)(sm + 11008);
    __nv_bfloat16* ph = (__nv_bfloat16*)(sm + 48384);
    __nv_bfloat16* pl = (__nv_bfloat16*)(sm + 49664);
    int s = blockIdx.x + s_off;
    if (blockIdx.y) b0 = 1;                  // 2D early grid: y = batch
    int bs = b0*S_ + s;
    int tid = threadIdx.x, lane = tid & 31, w = tid >> 5;
    const long kb = (long)b0 * 2048 * 576;
    int nchk = (s >> 5) + 1;
    if (nchk > 16) nchk = 16;

    if (s < ITOPK_) {
        for (int j = tid; j < 512; j += 512) tl[j] = j;
    } else {
        for (int j = tid; j < 512; j += 512) tl[j] = topk[(long)bs*512 + j];
    }
    if (tid < 16) { m_s[tid] = -1e30f; l_s[tid] = 0.f; }
    const float scale = 0.07216878364870322f;  // 1/sqrt(192)
    __syncthreads();
    for (int i = tid; i < 16*576; i += 512) {
        int h = i / 576, d = i - h*576;
        float v = (d < 512) ? qabs[(long)bs*8192 + h*512 + d]
                            : qfull[(long)bs*3072 + h*192 + 128 + (d - 512)];
        v *= scale;
        __nv_bfloat16 hi = __float2bfloat16_rn(v);
        qh[h*584 + d] = hi;
        qh[9344 + h*584 + d] = __float2bfloat16_rn(v - __bfloat162float(hi));  // ql region
    }
    at_gather(khi, klo, kb, tl, 0, sb + AT_BUF0, tid);
    __syncthreads();

    float oacc[4][4];
#pragma unroll
    for (int nt = 0; nt < 4; nt++)
#pragma unroll
        for (int r = 0; r < 4; r++) oacc[nt][r] = 0.f;

    int kh4 = w >> 2, nt4 = w & 3;
    int arow = lane & 15, ac = (lane >> 4) * 8;
    int brow = nt4*8 + (lane & 7), bc = ((lane >> 3) & 1) * 8;

    uint32_t ahq[9][4];
#pragma unroll
    for (int ks = 0; ks < 9; ks++) {
        int d = kh4*144 + ks*16;
        uint32_t ad = sb + 11008 + (arow*584 + d + ac)*2;
        LDSM_X4(ahq[ks], ad);
    }

    for (int c = 0; c < nchk; c++) {
        uint32_t buf = sb + AT_BUF0 + (c & 1)*AT_BUFSZ;
        if (c + 1 < nchk) {
            at_gather(khi, klo, kb, tl, c+1, sb + AT_BUF0 + ((c+1)&1)*AT_BUFSZ, tid);
            CP_WAIT(1);
        } else {
            CP_WAIT(0);
        }
        __syncthreads();

        float qk[4] = {0.f, 0.f, 0.f, 0.f};
#pragma unroll
        for (int ks = 0; ks < 9; ks++) {
            int d = kh4*144 + ks*16;
            uint32_t alr[4], bh[2], bl[2];
            uint32_t ad = sb + 11008 + (arow*584 + d + ac)*2;
            LDSM_X4(alr, ad + 18688);
            uint32_t bd = buf + (brow*584 + d + bc)*2;
            LDSM_X2(bh, bd);
            LDSM_X2(bl, bd + AT_LO);
            mma16816(qk, ahq[ks], bh);
            mma16816(qk, ahq[ks], bl);
            mma16816(qk, alr, bh);
        }
        {
            int m_ = lane >> 2, e0 = 2*(lane & 3);
            float* scr = sc + kh4*544;
            scr[m_*34 + nt4*8 + e0]       = qk[0];
            scr[m_*34 + nt4*8 + e0 + 1]   = qk[1];
            scr[(m_+8)*34 + nt4*8 + e0]   = qk[2];
            scr[(m_+8)*34 + nt4*8 + e0+1] = qk[3];
        }
        __syncthreads();

        {
            int t = tl[c*32 + lane];
            bool valid = (t <= s);
            int hh = w;
            float v = sc[hh*34 + lane] + sc[544 + hh*34 + lane]
                    + sc[1088 + hh*34 + lane] + sc[1632 + hh*34 + lane];
            float val = valid ? v : -1e30f;
            float mc = val;
#pragma unroll
            for (int o = 16; o > 0; o >>= 1) mc = fmaxf(mc, __shfl_xor_sync(0xffffffffu, mc, o));
            float m_old = m_s[hh];
            float m_new = fmaxf(m_old, mc);
            float a = expf(m_old - m_new);
            float p = valid ? expf(val - m_new) : 0.f;
            float psum = p;
#pragma unroll
            for (int o = 16; o > 0; o >>= 1) psum += __shfl_xor_sync(0xffffffffu, psum, o);
            if (lane == 0) { m_s[hh] = m_new; l_s[hh] = l_s[hh]*a + psum; al_s[hh] = a; }
            __nv_bfloat16 phi = __float2bfloat16_rn(p);
            ph[hh*40 + lane] = phi;
            pl[hh*40 + lane] = __float2bfloat16_rn(p - __bfloat162float(phi));
        }
        __syncthreads();

        {
            float a0 = al_s[lane >> 2], a1 = al_s[(lane >> 2) + 8];
#pragma unroll
            for (int nt = 0; nt < 4; nt++) {
                oacc[nt][0] *= a0; oacc[nt][1] *= a0;
                oacc[nt][2] *= a1; oacc[nt][3] *= a1;
            }
            uint32_t ph4[2][4], pl4[2][4];
#pragma unroll
            for (int ks = 0; ks < 2; ks++) {
                uint32_t ad = sb + 48384 + (arow*40 + ks*16 + ac)*2;
                LDSM_X4(ph4[ks], ad);
                LDSM_X4(pl4[ks], ad + 1280);
            }
#pragma unroll
            for (int nt = 0; nt < 4; nt++) {
                int n0 = w*32 + nt*8;
#pragma unroll
                for (int ks = 0; ks < 2; ks++) {
                    uint32_t bd = buf + ((ks*16 + (lane & 15))*584 + n0)*2;
                    uint32_t vh[2], vl[2];
                    LDSM_X2T(vh, bd);
                    LDSM_X2T(vl, bd + AT_LO);
                    mma16816(oacc[nt], ph4[ks], vh);
                    mma16816(oacc[nt], ph4[ks], vl);
                    mma16816(oacc[nt], pl4[ks], vh);
                }
            }
        }
        __syncthreads();
    }

    {
        int m_ = lane >> 2, e0 = 2*(lane & 3);
        float li0 = 1.f / l_s[m_];
        float li1 = 1.f / l_s[m_ + 8];
#pragma unroll
        for (int nt = 0; nt < 4; nt++) {
            int c0 = w*32 + nt*8 + e0;
            *(float2*)(omid + (long)bs*8192 + m_*512 + c0)     = make_float2(oacc[nt][0]*li0, oacc[nt][1]*li0);
            *(float2*)(omid + (long)bs*8192 + (m_+8)*512 + c0) = make_float2(oacc[nt][2]*li1, oacc[nt][3]*li1);
        }
    }
}

// ---------------- host orchestration (R13 schedule + dead-row removal) ---------
extern "C" void kernel_launch(void* const* d_in, const int* in_sizes, int n_in,
                              void* d_out, int out_size) {
    const float* x      = (const float*)d_in[0];
    const float* fcos   = (const float*)d_in[1];
    const float* fsin   = (const float*)d_in[2];
    const float* wq_a   = (const float*)d_in[4];
    const float* qnw    = (const float*)d_in[5];
    const float* wq_b   = (const float*)d_in[6];
    const float* wkv_a  = (const float*)d_in[7];
    const float* kvnw   = (const float*)d_in[8];
    const float* wkv_b  = (const float*)d_in[9];
    const float* wo     = (const float*)d_in[10];
    const float* iwqb   = (const float*)d_in[11];
    const float* iwk    = (const float*)d_in[12];
    const float* iknw   = (const float*)d_in[13];
    const float* iknb   = (const float*)d_in[14];
    const float* iwp    = (const float*)d_in[15];
    float* out = (float*)d_out;

    float *qr, *q, *kvfull, *kv, *kpe, *qabs, *qi, *ki, *wts, *iscore, *omid, *o2, *wt;
    __nv_bfloat16 *khi, *klo;
    int* topkb;
    cudaGetSymbolAddress((void**)&qr,     g_qr);
    cudaGetSymbolAddress((void**)&q,      g_q);
    cudaGetSymbolAddress((void**)&kvfull, g_kvfull);
    cudaGetSymbolAddress((void**)&kv,     g_kv);
    cudaGetSymbolAddress((void**)&kpe,    g_kpe);
    cudaGetSymbolAddress((void**)&qabs,   g_qabs);
    cudaGetSymbolAddress((void**)&qi,     g_qi);
    cudaGetSymbolAddress((void**)&ki,     g_ki);
    cudaGetSymbolAddress((void**)&wts,    g_wts);
    cudaGetSymbolAddress((void**)&iscore, g_iscore);
    cudaGetSymbolAddress((void**)&topkb,  g_topk);
    cudaGetSymbolAddress((void**)&omid,   g_omid);
    cudaGetSymbolAddress((void**)&o2,     g_o2);
    cudaGetSymbolAddress((void**)&wt,     g_wkvbT);
    cudaGetSymbolAddress((void**)&khi,    g_khi);
    cudaGetSymbolAddress((void**)&klo,    g_klo);

    cudaFuncSetAttribute(gemm_mma, cudaFuncAttributeMaxDynamicSharedMemorySize, GM_SMEM);
    cudaFuncSetAttribute(attn_tc,  cudaFuncAttributeMaxDynamicSharedMemorySize, AT_SMEM);

    static cudaStream_t s1 = 0, s2 = 0;
    static cudaEvent_t eF = 0, eQR = 0, eWT = 0, eT0 = 0, eT1 = 0;
    if (s1 == 0) {
        cudaStreamCreateWithFlags(&s1, cudaStreamNonBlocking);
        cudaStreamCreateWithFlags(&s2, cudaStreamNonBlocking);
        cudaEventCreateWithFlags(&eF,  cudaEventDisableTiming);
        cudaEventCreateWithFlags(&eQR, cudaEventDisableTiming);
        cudaEventCreateWithFlags(&eWT, cudaEventDisableTiming);
        cudaEventCreateWithFlags(&eT0, cudaEventDisableTiming);
        cudaEventCreateWithFlags(&eT1, cudaEventDisableTiming);
    }
    cudaStream_t s0 = 0;

    cudaEventRecord(eF, s0);
    cudaStreamWaitEvent(s1, eF, 0);
    cudaStreamWaitEvent(s2, eF, 0);

    // ---- s0: qr chain
    gemm_bt<<<dim3(6, 32, 1), 256, 0, s0>>>(x, 2048, 0, wq_a, 2048, 0, qr, 768, 0, 4096, 768, 2048);
    rmsnorm_kernel<<<4096, 256, 0, s0>>>(qr, qnw, 768);
    cudaEventRecord(eQR, s0);

    // ---- s2: kv path + weight transpose
    gemm_mma<<<dim3(5, 32, 1), 256, GM_SMEM, s2>>>(x, 2048, 0, wkv_a, 2048, 0, kvfull, 576, 0, 4096, 576, 2048);
    kvpost_kernel<<<4096, 256, 0, s2>>>(kvfull, kvnw, fcos, fsin, kv, kpe);
    kvsplit_kernel<<<(BS_*576 + 255)/256, 256, 0, s2>>>(kv, kpe, khi, klo);
    transpose_wkvb<<<(16*128*512 + 255)/256, 256, 0, s2>>>(wkv_b, wt);
    cudaEventRecord(eWT, s2);

    // ---- s1: indexer path, batch-split, dead rows (s<512) skipped
    gemm_bt<<<dim3(1, 32, 1), 256, 0, s1>>>(x, 2048, 0, iwk, 2048, 0, ki, 128, 0, 4096, 128, 2048);
    kipost_kernel<<<4096, 128, 0, s1>>>(ki, iknw, iknb, fcos, fsin);
    gemm_bt<<<dim3(1, 32, 1), 256, 0, s1>>>(x, 2048, 0, iwp, 2048, 0, wts, 16, 0, 4096, 16, 2048);
    cudaStreamWaitEvent(s1, eQR, 0);
    gemm_bt<<<dim3(16, 32, 1), 256, 0, s1>>>(qr, 768, 0, iwqb, 768, 0, qi, 2048, 0, 4096, 2048, 768);
    rope_qi_kernel<<<(BS_*16*32 + 255)/256, 256, 0, s1>>>(qi, fcos, fsin);
    iscore_kernel<<<dim3(32, 12, 1), 256, 0, s1>>>(qi, ki, wts, iscore, 512);
    topk_kernel<<<1536, 256, 0, s1>>>(iscore, topkb, 512);
    cudaEventRecord(eT0, s1);
    iscore_kernel<<<dim3(32, 12, 1), 256, 0, s1>>>(qi + (long)S_*2048, ki + (long)S_*128,
                                                   wts + (long)S_*16, iscore + (long)S_*S_, 512);
    topk_kernel<<<1536, 256, 0, s1>>>(iscore + (long)S_*S_, topkb + (long)S_*ITOPK_, 512);
    cudaEventRecord(eT1, s1);

    // ---- s0 continues: q chain, qabs, early attention (s<512, both batches),
    //      then main attention per batch + output tail
    gemm_mma<<<dim3(24, 32, 1), 256, GM_SMEM, s0>>>(qr, 768, 0, wq_b, 768, 0, q, 3072, 0, 4096, 3072, 768);
    rope_q_kernel<<<(BS_*16*32 + 255)/256, 256, 0, s0>>>(q, fcos, fsin);
    cudaStreamWaitEvent(s0, eWT, 0);
    gemm_mma<<<dim3(4, 32, 16), 256, GM_SMEM, s0>>>(q, 3072, 192, wt, 128, 65536, qabs, 8192, 512,
                                                    4096, 512, 128);
    attn_tc<<<dim3(512, 2, 1), 512, AT_SMEM, s0>>>(qabs, q, khi, klo, topkb, omid, 0, 0);
    cudaStreamWaitEvent(s0, eT0, 0);
    attn_tc<<<dim3(1536, 1, 1), 512, AT_SMEM, s0>>>(qabs, q, khi, klo, topkb, omid, 0, 512);
    cudaStreamWaitEvent(s0, eT1, 0);
    attn_tc<<<dim3(1536, 1, 1), 512, AT_SMEM, s0>>>(qabs, q, khi, klo, topkb, omid, 1, 512);
    gemm_mma<<<dim3(1, 32, 16), 256, GM_SMEM, s0>>>(omid, 8192, 512, wkv_b + 128*512, 512, 256*512,
                                                    o2, 2048, 128, 4096, 128, 512);
    gemm_mma<<<dim3(16, 32, 1), 256, GM_SMEM, s0>>>(o2, 2048, 0, wo, 2048, 0, out, 2048, 0, 4096, 2048, 2048);
}

// round 16
// speedup vs baseline: 1.0677x; 1.0179x over previous
#include <cuda_runtime.h>
#include <cuda_bf16.h>
#include <math.h>
#include <stdint.h>

// Problem constants
#define B_    2
#define S_    2048
#define DIM_  2048
#define NH_   16
#define QLR_  768
#define KVLR_ 512
#define NOPE_ 128
#define ROPE_ 64
#define VDIM_ 128
#define IH_   16
#define IHD_  128
#define ITOPK_ 512
#define BS_   (B_*S_)   // 4096

// ---------------- scratch (device globals; no allocation allowed) -------------
__device__ float g_qr[BS_*QLR_];
__device__ float g_q[BS_*NH_*(NOPE_+ROPE_)];
__device__ float g_kvfull[BS_*(KVLR_+ROPE_)];
__device__ float g_kv[BS_*KVLR_];
__device__ float g_kpe[BS_*ROPE_];
__device__ float g_qabs[BS_*NH_*KVLR_];
__device__ float g_qi[BS_*IH_*IHD_];
__device__ float g_ki[BS_*IHD_];
__device__ float g_wts[BS_*IH_];
__device__ float g_iscore[B_*S_*S_];
__device__ int   g_topk[BS_*ITOPK_];
__device__ float g_omid[BS_*NH_*KVLR_];
__device__ float g_o2[BS_*NH_*VDIM_];
__device__ float g_wkvbT[16*512*128];            // transposed wkv_b[:, :128, :] -> [h][c][d]
__device__ __nv_bfloat16 g_khi[BS_*576];         // kv||kpe hi split
__device__ __nv_bfloat16 g_klo[BS_*576];         // kv||kpe lo split

// =================== helpers ==================================================
__device__ __forceinline__ uint32_t smem_u32(const void* p) {
    uint32_t a;
    asm("{ .reg .u64 t; cvta.to.shared.u64 t, %1; cvt.u32.u64 %0, t; }" : "=r"(a) : "l"(p));
    return a;
}
__device__ __forceinline__ uint32_t pack_hi(float x, float y) {
    __nv_bfloat162 p;
    p.x = __float2bfloat16_rn(x);
    p.y = __float2bfloat16_rn(y);
    return *(uint32_t*)&p;
}
__device__ __forceinline__ uint32_t pack_lo(float x, float y) {
    __nv_bfloat16 hx = __float2bfloat16_rn(x);
    __nv_bfloat16 hy = __float2bfloat16_rn(y);
    __nv_bfloat162 p;
    p.x = __float2bfloat16_rn(x - __bfloat162float(hx));
    p.y = __float2bfloat16_rn(y - __bfloat162float(hy));
    return *(uint32_t*)&p;
}
__device__ __forceinline__ void mma16816(float* c, const uint32_t* a, const uint32_t* b) {
    asm volatile("mma.sync.aligned.m16n8k16.row.col.f32.bf16.bf16.f32 "
        "{%0,%1,%2,%3}, {%4,%5,%6,%7}, {%8,%9}, {%0,%1,%2,%3};"
        : "+f"(c[0]), "+f"(c[1]), "+f"(c[2]), "+f"(c[3])
        : "r"(a[0]), "r"(a[1]), "r"(a[2]), "r"(a[3]), "r"(b[0]), "r"(b[1]));
}
#define LDSM_X4(r, a) asm volatile("ldmatrix.sync.aligned.m8n8.x4.shared.b16 {%0,%1,%2,%3}, [%4];" \
    : "=r"((r)[0]),"=r"((r)[1]),"=r"((r)[2]),"=r"((r)[3]) : "r"(a))
#define LDSM_X2(r, a) asm volatile("ldmatrix.sync.aligned.m8n8.x2.shared.b16 {%0,%1}, [%2];" \
    : "=r"((r)[0]),"=r"((r)[1]) : "r"(a))
#define LDSM_X2T(r, a) asm volatile("ldmatrix.sync.aligned.m8n8.x2.trans.shared.b16 {%0,%1}, [%2];" \
    : "=r"((r)[0]),"=r"((r)[1]) : "r"(a))
#define CP_ASYNC16(dst, src) asm volatile("cp.async.cg.shared.global [%0], [%1], 16;" :: "r"(dst), "l"(src))
#define CP_COMMIT() asm volatile("cp.async.commit_group;" ::: "memory")
#define CP_WAIT(n)  asm volatile("cp.async.wait_group %0;" :: "n"(n) : "memory")

// word-granularity swizzled smem address for gemm_mma tiles (128 rows x 16 words)
__device__ __forceinline__ int sw_addr(int row, int w) {
    return row*16 + (w ^ ((((row)>>1)&3)<<2));
}

// =================== tensor-core GEMM (bf16x3): C[M,N]=A[M,K]@B[N,K]^T ========
#define GM_SMEM 65536

__global__ void __launch_bounds__(256, 1)
gemm_mma(const float* __restrict__ A, int lda, long aZ,
         const float* __restrict__ Bm, int ldb, long bZ,
         float* __restrict__ C, int ldc, long cZ,
         int M, int N, int K) {
    extern __shared__ uint32_t smw[];
    A  += (long)blockIdx.z * aZ;
    Bm += (long)blockIdx.z * bZ;
    C  += (long)blockIdx.z * cZ;
    int m0 = blockIdx.y * 128, n0 = blockIdx.x * 128;
    int tid = threadIdx.x, lane = tid & 31, wid = tid >> 5;
    int wm = wid >> 2, wn = wid & 3;
    int g = lane >> 2, tig = lane & 3;

    float acc[4][4][4];
#pragma unroll
    for (int i = 0; i < 4; i++)
#pragma unroll
        for (int j = 0; j < 4; j++)
#pragma unroll
            for (int r = 0; r < 4; r++) acc[i][j][r] = 0.f;

    int arow = tid >> 1, acol = (tid & 1) * 16;
    int nch = K >> 5;

    float4 ra[4], rb[4];
    {
        const float* ap = A + (long)(m0 + arow)*lda + acol;
        bool aok = (m0 + arow) < M;
#pragma unroll
        for (int i = 0; i < 4; i++)
            ra[i] = aok ? *(const float4*)(ap + i*4) : make_float4(0.f,0.f,0.f,0.f);
        const float* bp = Bm + (long)(n0 + arow)*ldb + acol;
        bool bok = (n0 + arow) < N;
#pragma unroll
        for (int i = 0; i < 4; i++)
            rb[i] = bok ? *(const float4*)(bp + i*4) : make_float4(0.f,0.f,0.f,0.f);
    }

    for (int it = 0; it < nch; it++) {
        int stg = it & 1;
        uint32_t* sAhi = smw + stg*8192;
        uint32_t* sAlo = sAhi + 2048;
        uint32_t* sBhi = sAhi + 4096;
        uint32_t* sBlo = sAhi + 6144;
        {
            uint32_t hw[8], lw[8];
#pragma unroll
            for (int i = 0; i < 4; i++) {
                hw[i*2]   = pack_hi(ra[i].x, ra[i].y);
                hw[i*2+1] = pack_hi(ra[i].z, ra[i].w);
                lw[i*2]   = pack_lo(ra[i].x, ra[i].y);
                lw[i*2+1] = pack_lo(ra[i].z, ra[i].w);
            }
            int g0 = (((tid&1)*2 + 0) ^ ((arow>>1)&3)) * 4;
            int g1 = (((tid&1)*2 + 1) ^ ((arow>>1)&3)) * 4;
            uint32_t* dst = sAhi + arow*16;
            *(uint4*)(dst + g0) = make_uint4(hw[0],hw[1],hw[2],hw[3]);
            *(uint4*)(dst + g1) = make_uint4(hw[4],hw[5],hw[6],hw[7]);
            dst = sAlo + arow*16;
            *(uint4*)(dst + g0) = make_uint4(lw[0],lw[1],lw[2],lw[3]);
            *(uint4*)(dst + g1) = make_uint4(lw[4],lw[5],lw[6],lw[7]);
#pragma unroll
            for (int i = 0; i < 4; i++) {
                hw[i*2]   = pack_hi(rb[i].x, rb[i].y);
                hw[i*2+1] = pack_hi(rb[i].z, rb[i].w);
                lw[i*2]   = pack_lo(rb[i].x, rb[i].y);
                lw[i*2+1] = pack_lo(rb[i].z, rb[i].w);
            }
            dst = sBhi + arow*16;
            *(uint4*)(dst + g0) = make_uint4(hw[0],hw[1],hw[2],hw[3]);
            *(uint4*)(dst + g1) = make_uint4(hw[4],hw[5],hw[6],hw[7]);
            dst = sBlo + arow*16;
            *(uint4*)(dst + g0) = make_uint4(lw[0],lw[1],lw[2],lw[3]);
            *(uint4*)(dst + g1) = make_uint4(lw[4],lw[5],lw[6],lw[7]);
        }
        __syncthreads();
        if (it + 1 < nch) {
            int gk = (it + 1) << 5;
            const float* ap = A + (long)(m0 + arow)*lda + gk + acol;
            bool aok = (m0 + arow) < M;
#pragma unroll
            for (int i = 0; i < 4; i++)
                ra[i] = aok ? *(const float4*)(ap + i*4) : make_float4(0.f,0.f,0.f,0.f);
            const float* bp = Bm + (long)(n0 + arow)*ldb + gk + acol;
            bool bok = (n0 + arow) < N;
#pragma unroll
            for (int i = 0; i < 4; i++)
                rb[i] = bok ? *(const float4*)(bp + i*4) : make_float4(0.f,0.f,0.f,0.f);
        }
#pragma unroll
        for (int ks = 0; ks < 2; ks++) {
            uint32_t bh[4][2], bl[4][2];
#pragma unroll
            for (int nt = 0; nt < 4; nt++) {
                int nrow = wn*32 + nt*8 + g;
                int w0 = ks*8 + tig;
                bh[nt][0] = sBhi[sw_addr(nrow, w0)];
                bh[nt][1] = sBhi[sw_addr(nrow, w0+4)];
                bl[nt][0] = sBlo[sw_addr(nrow, w0)];
                bl[nt][1] = sBlo[sw_addr(nrow, w0+4)];
            }
#pragma unroll
            for (int mt = 0; mt < 4; mt++) {
                int ar = wm*64 + mt*16 + g;
                int w0 = ks*8 + tig;
                uint32_t ah[4], al[4];
                ah[0] = sAhi[sw_addr(ar,   w0)];
                ah[1] = sAhi[sw_addr(ar+8, w0)];
                ah[2] = sAhi[sw_addr(ar,   w0+4)];
                ah[3] = sAhi[sw_addr(ar+8, w0+4)];
                al[0] = sAlo[sw_addr(ar,   w0)];
                al[1] = sAlo[sw_addr(ar+8, w0)];
                al[2] = sAlo[sw_addr(ar,   w0+4)];
                al[3] = sAlo[sw_addr(ar+8, w0+4)];
#pragma unroll
                for (int nt = 0; nt < 4; nt++) {
                    mma16816(acc[mt][nt], ah, bh[nt]);
                    mma16816(acc[mt][nt], ah, bl[nt]);
                    mma16816(acc[mt][nt], al, bh[nt]);
                }
            }
        }
        __syncthreads();
    }
#pragma unroll
    for (int mt = 0; mt < 4; mt++) {
#pragma unroll
        for (int nt = 0; nt < 4; nt++) {
            int r0 = m0 + wm*64 + mt*16 + g;
            int c0 = n0 + wn*32 + nt*8 + tig*2;
            if (c0 < N) {
                if (r0 < M)
                    *(float2*)(C + (long)r0*ldc + c0) = make_float2(acc[mt][nt][0], acc[mt][nt][1]);
                if (r0 + 8 < M)
                    *(float2*)(C + (long)(r0+8)*ldc + c0) = make_float2(acc[mt][nt][2], acc[mt][nt][3]);
            }
        }
    }
}

// transpose wkv_b[:, :128, :] -> wt[h][c][d]
__global__ void transpose_wkvb(const float* __restrict__ w, float* __restrict__ wt) {
    int idx = blockIdx.x * 256 + threadIdx.x;
    if (idx >= 16*128*512) return;
    int c = idx & 511, d = (idx >> 9) & 127, h = idx >> 16;
    wt[h*65536 + c*128 + d] = w[h*131072 + d*512 + c];
}

// ---------------- fp32 GEMM (bit-exact k-order, float4 loads) ------------------
__global__ void __launch_bounds__(256)
gemm_bt(const float* __restrict__ A, int lda, long aZ,
        const float* __restrict__ Bm, int ldb, long bZ,
        float* __restrict__ C, int ldc, long cZ,
        int M, int N, int K) {
    A  += (long)blockIdx.z * aZ;
    Bm += (long)blockIdx.z * bZ;
    C  += (long)blockIdx.z * cZ;
    int n0 = blockIdx.x * 128, m0 = blockIdx.y * 128;
    __shared__ float As[16][129];
    __shared__ float Bs[16][129];
    int tid = threadIdx.x;
    int tx = tid & 15, ty = tid >> 4;
    int lq = tid & 3, lm = tid >> 2;     // float4 load indices: k-quad, row
    float acc[8][8];
#pragma unroll
    for (int i = 0; i < 8; i++)
#pragma unroll
        for (int j = 0; j < 8; j++) acc[i][j] = 0.f;

    for (int k0 = 0; k0 < K; k0 += 16) {
#pragma unroll
        for (int p = 0; p < 2; p++) {
            int m = lm + 64*p;
            float4 va = *(const float4*)(A + (long)(m0 + m)*lda + k0 + lq*4);
            As[lq*4+0][m] = va.x; As[lq*4+1][m] = va.y;
            As[lq*4+2][m] = va.z; As[lq*4+3][m] = va.w;
            int gn = n0 + m;
            float4 vb = (gn < N) ? *(const float4*)(Bm + (long)gn*ldb + k0 + lq*4)
                                 : make_float4(0.f,0.f,0.f,0.f);
            Bs[lq*4+0][m] = vb.x; Bs[lq*4+1][m] = vb.y;
            Bs[lq*4+2][m] = vb.z; Bs[lq*4+3][m] = vb.w;
        }
        __syncthreads();
#pragma unroll
        for (int kk = 0; kk < 16; kk++) {
            float a[8], bb[8];
#pragma unroll
            for (int i = 0; i < 8; i++) a[i]  = As[kk][ty + 16*i];
#pragma unroll
            for (int j = 0; j < 8; j++) bb[j] = Bs[kk][tx + 16*j];
#pragma unroll
            for (int i = 0; i < 8; i++)
#pragma unroll
                for (int j = 0; j < 8; j++) acc[i][j] += a[i]*bb[j];
        }
        __syncthreads();
    }
#pragma unroll
    for (int i = 0; i < 8; i++)
#pragma unroll
        for (int j = 0; j < 8; j++) {
            int gm = m0 + ty + 16*i, gn = n0 + tx + 16*j;
            if (gm < M && gn < N) C[(long)gm*ldc + gn] = acc[i][j];
        }
}

// ---------------- elementwise / norm / rope -----------------------------------
__global__ void rmsnorm_kernel(float* __restrict__ x, const float* __restrict__ w, int L) {
    int row = blockIdx.x, tid = threadIdx.x;
    float* pr = x + (long)row * L;
    float ss = 0.f;
    for (int i = tid; i < L; i += 256) { float v = pr[i]; ss += v*v; }
    __shared__ float red[256];
    red[tid] = ss; __syncthreads();
    for (int o = 128; o > 0; o >>= 1) { if (tid < o) red[tid] += red[tid+o]; __syncthreads(); }
    float inv = rsqrtf(red[0] / (float)L + 1e-6f);
    for (int i = tid; i < L; i += 256) pr[i] = w[i] * pr[i] * inv;
}

__global__ void kvpost_kernel(const float* __restrict__ kvfull, const float* __restrict__ w,
                              const float* __restrict__ fcos, const float* __restrict__ fsin,
                              float* __restrict__ kv, float* __restrict__ kpe) {
    int row = blockIdx.x, s = row & (S_-1), tid = threadIdx.x;
    const float* src = kvfull + (long)row * 576;
    float ss = 0.f;
    for (int i = tid; i < 512; i += 256) { float v = src[i]; ss += v*v; }
    __shared__ float red[256];
    red[tid] = ss; __syncthreads();
    for (int o = 128; o > 0; o >>= 1) { if (tid < o) red[tid] += red[tid+o]; __syncthreads(); }
    float inv = rsqrtf(red[0] / 512.f + 1e-6f);
    for (int i = tid; i < 512; i += 256) kv[(long)row*512 + i] = w[i] * src[i] * inv;
    if (tid < 32) {
        float x1 = src[512 + tid], x2 = src[544 + tid];
        float c = fcos[s*32 + tid], sn = fsin[s*32 + tid];
        kpe[(long)row*64 + tid]      = x1*c - x2*sn;
        kpe[(long)row*64 + 32 + tid] = x1*sn + x2*c;
    }
}

// split kv||kpe into bf16 hi/lo global arrays
__global__ void kvsplit_kernel(const float* __restrict__ kv, const float* __restrict__ kpe,
                               __nv_bfloat16* __restrict__ khi, __nv_bfloat16* __restrict__ klo) {
    int idx = blockIdx.x*256 + threadIdx.x;
    if (idx >= BS_*576) return;
    int r = idx / 576, d = idx - r*576;
    float v = (d < 512) ? kv[(long)r*512 + d] : kpe[(long)r*64 + d - 512];
    __nv_bfloat16 hi = __float2bfloat16_rn(v);
    khi[idx] = hi;
    klo[idx] = __float2bfloat16_rn(v - __bfloat162float(hi));
}

__global__ void kipost_kernel(float* __restrict__ ki, const float* __restrict__ w,
                              const float* __restrict__ bvec,
                              const float* __restrict__ fcos, const float* __restrict__ fsin) {
    int row = blockIdx.x, s = row & (S_-1), tid = threadIdx.x; // 128 threads
    float* pr = ki + (long)row * 128;
    float v = pr[tid];
    __shared__ float red[128];
    red[tid] = v; __syncthreads();
    for (int o = 64; o > 0; o >>= 1) { if (tid < o) red[tid] += red[tid+o]; __syncthreads(); }
    float mean = red[0] / 128.f;
    __syncthreads();
    float d = v - mean;
    red[tid] = d*d; __syncthreads();
    for (int o = 64; o > 0; o >>= 1) { if (tid < o) red[tid] += red[tid+o]; __syncthreads(); }
    float var = red[0] / 128.f;
    __syncthreads();
    float y = d * rsqrtf(var + 1e-6f) * w[tid] + bvec[tid];
    __shared__ float yb[128];
    yb[tid] = y; __syncthreads();
    float outv;
    if (tid < 32) {
        float c = fcos[s*32 + tid], sn = fsin[s*32 + tid];
        outv = yb[tid]*c - yb[tid+32]*sn;
    } else if (tid < 64) {
        int i = tid - 32;
        float c = fcos[s*32 + i], sn = fsin[s*32 + i];
        outv = yb[i]*sn + yb[tid]*c;
    } else {
        outv = y;
    }
    pr[tid] = outv;
}

__global__ void rope_q_kernel(float* __restrict__ q, const float* __restrict__ fcos,
                              const float* __restrict__ fsin) {
    int idx = blockIdx.x * blockDim.x + threadIdx.x;
    if (idx >= BS_*16*32) return;
    int i = idx & 31, h = (idx >> 5) & 15, bs = idx >> 9;
    int s = bs & (S_-1);
    long base = (long)bs*3072 + h*192 + 128;
    float x1 = q[base + i], x2 = q[base + 32 + i];
    float c = fcos[s*32 + i], sn = fsin[s*32 + i];
    q[base + i]      = x1*c - x2*sn;
    q[base + 32 + i] = x1*sn + x2*c;
}

__global__ void rope_qi_kernel(float* __restrict__ qi, const float* __restrict__ fcos,
                               const float* __restrict__ fsin) {
    int idx = blockIdx.x * blockDim.x + threadIdx.x;
    if (idx >= BS_*16*32) return;
    int i = idx & 31, h = (idx >> 5) & 15, bs = idx >> 9;
    int s = bs & (S_-1);
    long base = (long)bs*2048 + h*128;
    float x1 = qi[base + i], x2 = qi[base + 32 + i];
    float c = fcos[s*32 + i], sn = fsin[s*32 + i];
    qi[base + i]      = x1*c - x2*sn;
    qi[base + 32 + i] = x1*sn + x2*c;
}

// ---------------- indexer score (128s x 64t tile, 2 heads/pass, bit-exact) ----
__global__ void __launch_bounds__(256)
iscore_kernel(const float* __restrict__ qi, const float* __restrict__ ki,
              const float* __restrict__ wts, float* __restrict__ iscore, int s_base) {
    int s0 = s_base + blockIdx.y * 128, t0 = blockIdx.x * 64;
    int tid = threadIdx.x;
    if (t0 > s0 + 127) return;   // fully-masked tile: never read downstream
    int tx = tid & 15, ty = tid >> 4;
    int lq = tid & 3, lm = tid >> 2;
    __shared__ float qs[2][16][129];
    __shared__ float ks[16][65];
    __shared__ float ws_s[16][128];
    const float IW_SCALE = rsqrtf(2048.0f);
    for (int i = tid; i < 16*128; i += 256) {
        int m = i >> 4, h = i & 15;
        ws_s[h][m] = wts[((long)(s0 + m))*16 + h] * IW_SCALE;
    }
    float acc[8][4];
#pragma unroll
    for (int i = 0; i < 8; i++)
#pragma unroll
        for (int j = 0; j < 4; j++) acc[i][j] = 0.f;
    __syncthreads();

    for (int h = 0; h < 16; h += 2) {
        float dot[2][8][4];
#pragma unroll
        for (int e = 0; e < 2; e++)
#pragma unroll
            for (int i = 0; i < 8; i++)
#pragma unroll
                for (int j = 0; j < 4; j++) dot[e][i][j] = 0.f;
        for (int d0 = 0; d0 < 128; d0 += 16) {
#pragma unroll
            for (int e = 0; e < 2; e++)
#pragma unroll
                for (int p = 0; p < 2; p++) {
                    int m = lm + 64*p;
                    float4 v = *(const float4*)(qi + ((long)(s0 + m))*2048 + (h+e)*128 + d0 + lq*4);
                    qs[e][lq*4+0][m] = v.x; qs[e][lq*4+1][m] = v.y;
                    qs[e][lq*4+2][m] = v.z; qs[e][lq*4+3][m] = v.w;
                }
            {
                float4 v = *(const float4*)(ki + ((long)(t0 + lm))*128 + d0 + lq*4);
                ks[lq*4+0][lm] = v.x; ks[lq*4+1][lm] = v.y;
                ks[lq*4+2][lm] = v.z; ks[lq*4+3][lm] = v.w;
            }
            __syncthreads();
#pragma unroll
            for (int kk = 0; kk < 16; kk++) {
                float a0[8], a1[8], bb[4];
#pragma unroll
                for (int i = 0; i < 8; i++) { a0[i] = qs[0][kk][ty + 16*i]; a1[i] = qs[1][kk][ty + 16*i]; }
#pragma unroll
                for (int j = 0; j < 4; j++) bb[j] = ks[kk][tx + 16*j];
#pragma unroll
                for (int i = 0; i < 8; i++)
#pragma unroll
                    for (int j = 0; j < 4; j++) {
                        dot[0][i][j] += a0[i]*bb[j];
                        dot[1][i][j] += a1[i]*bb[j];
                    }
            }
            __syncthreads();
        }
#pragma unroll
        for (int e = 0; e < 2; e++)
#pragma unroll
            for (int i = 0; i < 8; i++) {
                float w = ws_s[h+e][ty + 16*i];
#pragma unroll
                for (int j = 0; j < 4; j++) acc[i][j] += fmaxf(dot[e][i][j], 0.f) * w;
            }
    }
#pragma unroll
    for (int i = 0; i < 8; i++)
#pragma unroll
        for (int j = 0; j < 4; j++) {
            int s = s0 + ty + 16*i, t = t0 + tx + 16*j;
            float mval = (t <= s) ? 0.f : -1000000000.0f;
            iscore[((long)s)*S_ + t] = acc[i][j] + mval;
        }
}

// ---------------- exact top-512 per row (prefix-only radix, deterministic) ----
__global__ void topk_kernel(const float* __restrict__ iscore, int* __restrict__ out, int s_off) {
    int s = blockIdx.x + s_off;
    int tid = threadIdx.x; // 256
    int* o = out + (long)s * ITOPK_;
    const float* p = iscore + (long)s * S_;
    __shared__ unsigned int hist[256];
    __shared__ unsigned int s_prefix;
    __shared__ int s_rem;
    __shared__ int sgt[257], seq[257];
    if (tid == 0) { s_prefix = 0u; s_rem = ITOPK_; }
    __syncthreads();
    for (int pass = 0; pass < 4; pass++) {
        hist[tid] = 0u;
        __syncthreads();
        int shift = 24 - 8*pass;
        unsigned int pref = s_prefix;
        for (int e = 0; e < 8; e++) {
            int j = tid*8 + e;
            if (j > s) break;
            unsigned int u = __float_as_uint(p[j]);
            unsigned int k = (u & 0x80000000u) ? ~u : (u | 0x80000000u);
            bool ok = (pass == 0) || (((k ^ pref) >> (shift + 8)) == 0u);
            if (ok) atomicAdd(&hist[(k >> shift) & 255u], 1u);
        }
        __syncthreads();
        if (tid == 0) {
            int rem = s_rem;
            unsigned int cum = 0; int bin = 0;
            for (int bb = 255; bb >= 0; bb--) {
                if (cum + hist[bb] >= (unsigned)rem) { bin = bb; break; }
                cum += hist[bb];
            }
            s_rem = rem - (int)cum;
            s_prefix = s_prefix | ((unsigned)bin << shift);
        }
        __syncthreads();
    }
    unsigned int kth = s_prefix;
    int cgt = 0, ceq = 0;
    for (int e = 0; e < 8; e++) {
        int j = tid*8 + e;
        if (j > s) break;
        unsigned int u = __float_as_uint(p[j]);
        unsigned int k = (u & 0x80000000u) ? ~u : (u | 0x80000000u);
        cgt += (k > kth); ceq += (k == kth);
    }
    sgt[tid] = cgt; seq[tid] = ceq;
    __syncthreads();
    if (tid == 0) {
        int ag = 0, ae = 0;
        for (int i = 0; i < 256; i++) {
            int tg = sgt[i], te = seq[i];
            sgt[i] = ag; seq[i] = ae;
            ag += tg; ae += te;
        }
        sgt[256] = ag;
    }
    __syncthreads();
    int total_gt = sgt[256];
    int pgt = sgt[tid];
    int peq = total_gt + seq[tid];
    for (int e = 0; e < 8; e++) {
        int j = tid*8 + e;
        if (j > s) break;
        unsigned int u = __float_as_uint(p[j]);
        unsigned int k = (u & 0x80000000u) ? ~u : (u | 0x80000000u);
        if (k > kth) { o[pgt++] = j; }
        else if (k == kth) { if (peq < ITOPK_) o[peq] = j; peq++; }
    }
}

// ---------------- fused flash-style tensor-core sparse attention ---------------
// 512 threads / 16 warps. BOTH Q hi and Q lo fragments hoisted into registers
// (loop-invariant across chunks); all-invalid chunks skipped; rows s<512
// synthesize tl[j]=j (identical to topk output) -> no topk dependency.
#define AT_SMEM 200448
#define AT_BUF0 50944
#define AT_BUFSZ 74752
#define AT_LO 37376

__device__ __forceinline__ void at_gather(const __nv_bfloat16* __restrict__ khi,
                                          const __nv_bfloat16* __restrict__ klo,
                                          long kb, const int* tl, int c,
                                          uint32_t bufaddr, int tid) {
    int jloc = tid >> 4, sg0 = tid & 15;   // 32 rows x 16 threads
    int t = tl[c*32 + jloc];
    const char* sh = (const char*)(khi + kb + (long)t*576);
    const char* sl = (const char*)(klo + kb + (long)t*576);
    uint32_t dh = bufaddr + jloc*1168;
#pragma unroll
    for (int u = 0; u < 9; u++) {
        int ch = sg0 + u*16;               // 0..143: 72 hi chunks then 72 lo
        if (ch < 72) CP_ASYNC16(dh + ch*16, sh + ch*16);
        else         CP_ASYNC16(dh + AT_LO + (ch-72)*16, sl + (ch-72)*16);
    }
    CP_COMMIT();
}

__global__ void __launch_bounds__(512, 1)
attn_tc(const float* __restrict__ qabs, const float* __restrict__ qfull,
        const __nv_bfloat16* __restrict__ khi, const __nv_bfloat16* __restrict__ klo,
        const int* __restrict__ topk, float* __restrict__ omid, int b0, int s_off) {
    extern __shared__ char sm[];
    uint32_t sb = smem_u32(sm);
    int* tl = (int*)sm;
    float* m_s  = (float*)(sm + 2048);
    float* l_s  = (float*)(sm + 2112);
    float* al_s = (float*)(sm + 2176);
    float* sc   = (float*)(sm + 2304);       // [4][16][34]
    __nv_bfloat16* qh = (__nv_bfloat16*)(sm + 11008);
    __nv_bfloat16* ph = (__nv_bfloat16*)(sm + 48384);
    __nv_bfloat16* pl = (__nv_bfloat16*)(sm + 49664);
    int s = blockIdx.x + s_off;
    if (blockIdx.y) b0 = 1;                  // 2D early grid: y = batch
    int bs = b0*S_ + s;
    int tid = threadIdx.x, lane = tid & 31, w = tid >> 5;
    const long kb = (long)b0 * 2048 * 576;
    int nchk = (s >> 5) + 1;
    if (nchk > 16) nchk = 16;

    if (s < ITOPK_) {
        for (int j = tid; j < 512; j += 512) tl[j] = j;
    } else {
        for (int j = tid; j < 512; j += 512) tl[j] = topk[(long)bs*512 + j];
    }
    if (tid < 16) { m_s[tid] = -1e30f; l_s[tid] = 0.f; }
    const float scale = 0.07216878364870322f;  // 1/sqrt(192)
    __syncthreads();
    for (int i = tid; i < 16*576; i += 512) {
        int h = i / 576, d = i - h*576;
        float v = (d < 512) ? qabs[(long)bs*8192 + h*512 + d]
                            : qfull[(long)bs*3072 + h*192 + 128 + (d - 512)];
        v *= scale;
        __nv_bfloat16 hi = __float2bfloat16_rn(v);
        qh[h*584 + d] = hi;
        qh[9344 + h*584 + d] = __float2bfloat16_rn(v - __bfloat162float(hi));  // ql region
    }
    at_gather(khi, klo, kb, tl, 0, sb + AT_BUF0, tid);
    __syncthreads();

    float oacc[4][4];
#pragma unroll
    for (int nt = 0; nt < 4; nt++)
#pragma unroll
        for (int r = 0; r < 4; r++) oacc[nt][r] = 0.f;

    int kh4 = w >> 2, nt4 = w & 3;
    int arow = lane & 15, ac = (lane >> 4) * 8;
    int brow = nt4*8 + (lane & 7), bc = ((lane >> 3) & 1) * 8;

    // ---- hoist BOTH Q hi and Q lo fragments (loop-invariant across chunks)
    uint32_t ahq[9][4], alq[9][4];
#pragma unroll
    for (int ks = 0; ks < 9; ks++) {
        int d = kh4*144 + ks*16;
        uint32_t ad = sb + 11008 + (arow*584 + d + ac)*2;
        LDSM_X4(ahq[ks], ad);
        LDSM_X4(alq[ks], ad + 18688);
    }

    for (int c = 0; c < nchk; c++) {
        uint32_t buf = sb + AT_BUF0 + (c & 1)*AT_BUFSZ;
        if (c + 1 < nchk) {
            at_gather(khi, klo, kb, tl, c+1, sb + AT_BUF0 + ((c+1)&1)*AT_BUFSZ, tid);
            CP_WAIT(1);
        } else {
            CP_WAIT(0);
        }
        __syncthreads();

        float qk[4] = {0.f, 0.f, 0.f, 0.f};
#pragma unroll
        for (int ks = 0; ks < 9; ks++) {
            int d = kh4*144 + ks*16;
            uint32_t bh[2], bl[2];
            uint32_t bd = buf + (brow*584 + d + bc)*2;
            LDSM_X2(bh, bd);
            LDSM_X2(bl, bd + AT_LO);
            mma16816(qk, ahq[ks], bh);
            mma16816(qk, ahq[ks], bl);
            mma16816(qk, alq[ks], bh);
        }
        {
            int m_ = lane >> 2, e0 = 2*(lane & 3);
            float* scr = sc + kh4*544;
            scr[m_*34 + nt4*8 + e0]       = qk[0];
            scr[m_*34 + nt4*8 + e0 + 1]   = qk[1];
            scr[(m_+8)*34 + nt4*8 + e0]   = qk[2];
            scr[(m_+8)*34 + nt4*8 + e0+1] = qk[3];
        }
        __syncthreads();

        {
            int t = tl[c*32 + lane];
            bool valid = (t <= s);
            int hh = w;
            float v = sc[hh*34 + lane] + sc[544 + hh*34 + lane]
                    + sc[1088 + hh*34 + lane] + sc[1632 + hh*34 + lane];
            float val = valid ? v : -1e30f;
            float mc = val;
#pragma unroll
            for (int o = 16; o > 0; o >>= 1) mc = fmaxf(mc, __shfl_xor_sync(0xffffffffu, mc, o));
            float m_old = m_s[hh];
            float m_new = fmaxf(m_old, mc);
            float a = expf(m_old - m_new);
            float p = valid ? expf(val - m_new) : 0.f;
            float psum = p;
#pragma unroll
            for (int o = 16; o > 0; o >>= 1) psum += __shfl_xor_sync(0xffffffffu, psum, o);
            if (lane == 0) { m_s[hh] = m_new; l_s[hh] = l_s[hh]*a + psum; al_s[hh] = a; }
            __nv_bfloat16 phi = __float2bfloat16_rn(p);
            ph[hh*40 + lane] = phi;
            pl[hh*40 + lane] = __float2bfloat16_rn(p - __bfloat162float(phi));
        }
        __syncthreads();

        {
            float a0 = al_s[lane >> 2], a1 = al_s[(lane >> 2) + 8];
#pragma unroll
            for (int nt = 0; nt < 4; nt++) {
                oacc[nt][0] *= a0; oacc[nt][1] *= a0;
                oacc[nt][2] *= a1; oacc[nt][3] *= a1;
            }
            uint32_t ph4[2][4], pl4[2][4];
#pragma unroll
            for (int ks = 0; ks < 2; ks++) {
                uint32_t ad = sb + 48384 + (arow*40 + ks*16 + ac)*2;
                LDSM_X4(ph4[ks], ad);
                LDSM_X4(pl4[ks], ad + 1280);
            }
#pragma unroll
            for (int nt = 0; nt < 4; nt++) {
                int n0 = w*32 + nt*8;
#pragma unroll
                for (int ks = 0; ks < 2; ks++) {
                    uint32_t bd = buf + ((ks*16 + (lane & 15))*584 + n0)*2;
                    uint32_t vh[2], vl[2];
                    LDSM_X2T(vh, bd);
                    LDSM_X2T(vl, bd + AT_LO);
                    mma16816(oacc[nt], ph4[ks], vh);
                    mma16816(oacc[nt], ph4[ks], vl);
                    mma16816(oacc[nt], pl4[ks], vh);
                }
            }
        }
        __syncthreads();
    }

    {
        int m_ = lane >> 2, e0 = 2*(lane & 3);
        float li0 = 1.f / l_s[m_];
        float li1 = 1.f / l_s[m_ + 8];
#pragma unroll
        for (int nt = 0; nt < 4; nt++) {
            int c0 = w*32 + nt*8 + e0;
            *(float2*)(omid + (long)bs*8192 + m_*512 + c0)     = make_float2(oacc[nt][0]*li0, oacc[nt][1]*li0);
            *(float2*)(omid + (long)bs*8192 + (m_+8)*512 + c0) = make_float2(oacc[nt][2]*li1, oacc[nt][3]*li1);
        }
    }
}

// ---------------- host orchestration (R15 schedule) ----------------------------
extern "C" void kernel_launch(void* const* d_in, const int* in_sizes, int n_in,
                              void* d_out, int out_size) {
    const float* x      = (const float*)d_in[0];
    const float* fcos   = (const float*)d_in[1];
    const float* fsin   = (const float*)d_in[2];
    const float* wq_a   = (const float*)d_in[4];
    const float* qnw    = (const float*)d_in[5];
    const float* wq_b   = (const float*)d_in[6];
    const float* wkv_a  = (const float*)d_in[7];
    const float* kvnw   = (const float*)d_in[8];
    const float* wkv_b  = (const float*)d_in[9];
    const float* wo     = (const float*)d_in[10];
    const float* iwqb   = (const float*)d_in[11];
    const float* iwk    = (const float*)d_in[12];
    const float* iknw   = (const float*)d_in[13];
    const float* iknb   = (const float*)d_in[14];
    const float* iwp    = (const float*)d_in[15];
    float* out = (float*)d_out;

    float *qr, *q, *kvfull, *kv, *kpe, *qabs, *qi, *ki, *wts, *iscore, *omid, *o2, *wt;
    __nv_bfloat16 *khi, *klo;
    int* topkb;
    cudaGetSymbolAddress((void**)&qr,     g_qr);
    cudaGetSymbolAddress((void**)&q,      g_q);
    cudaGetSymbolAddress((void**)&kvfull, g_kvfull);
    cudaGetSymbolAddress((void**)&kv,     g_kv);
    cudaGetSymbolAddress((void**)&kpe,    g_kpe);
    cudaGetSymbolAddress((void**)&qabs,   g_qabs);
    cudaGetSymbolAddress((void**)&qi,     g_qi);
    cudaGetSymbolAddress((void**)&ki,     g_ki);
    cudaGetSymbolAddress((void**)&wts,    g_wts);
    cudaGetSymbolAddress((void**)&iscore, g_iscore);
    cudaGetSymbolAddress((void**)&topkb,  g_topk);
    cudaGetSymbolAddress((void**)&omid,   g_omid);
    cudaGetSymbolAddress((void**)&o2,     g_o2);
    cudaGetSymbolAddress((void**)&wt,     g_wkvbT);
    cudaGetSymbolAddress((void**)&khi,    g_khi);
    cudaGetSymbolAddress((void**)&klo,    g_klo);

    cudaFuncSetAttribute(gemm_mma, cudaFuncAttributeMaxDynamicSharedMemorySize, GM_SMEM);
    cudaFuncSetAttribute(attn_tc,  cudaFuncAttributeMaxDynamicSharedMemorySize, AT_SMEM);

    static cudaStream_t s1 = 0, s2 = 0;
    static cudaEvent_t eF = 0, eQR = 0, eWT = 0, eT0 = 0, eT1 = 0;
    if (s1 == 0) {
        cudaStreamCreateWithFlags(&s1, cudaStreamNonBlocking);
        cudaStreamCreateWithFlags(&s2, cudaStreamNonBlocking);
        cudaEventCreateWithFlags(&eF,  cudaEventDisableTiming);
        cudaEventCreateWithFlags(&eQR, cudaEventDisableTiming);
        cudaEventCreateWithFlags(&eWT, cudaEventDisableTiming);
        cudaEventCreateWithFlags(&eT0, cudaEventDisableTiming);
        cudaEventCreateWithFlags(&eT1, cudaEventDisableTiming);
    }
    cudaStream_t s0 = 0;

    cudaEventRecord(eF, s0);
    cudaStreamWaitEvent(s1, eF, 0);
    cudaStreamWaitEvent(s2, eF, 0);

    // ---- s0: qr chain
    gemm_bt<<<dim3(6, 32, 1), 256, 0, s0>>>(x, 2048, 0, wq_a, 2048, 0, qr, 768, 0, 4096, 768, 2048);
    rmsnorm_kernel<<<4096, 256, 0, s0>>>(qr, qnw, 768);
    cudaEventRecord(eQR, s0);

    // ---- s2: kv path + weight transpose
    gemm_mma<<<dim3(5, 32, 1), 256, GM_SMEM, s2>>>(x, 2048, 0, wkv_a, 2048, 0, kvfull, 576, 0, 4096, 576, 2048);
    kvpost_kernel<<<4096, 256, 0, s2>>>(kvfull, kvnw, fcos, fsin, kv, kpe);
    kvsplit_kernel<<<(BS_*576 + 255)/256, 256, 0, s2>>>(kv, kpe, khi, klo);
    transpose_wkvb<<<(16*128*512 + 255)/256, 256, 0, s2>>>(wkv_b, wt);
    cudaEventRecord(eWT, s2);

    // ---- s1: indexer path, batch-split, dead rows (s<512) skipped
    gemm_bt<<<dim3(1, 32, 1), 256, 0, s1>>>(x, 2048, 0, iwk, 2048, 0, ki, 128, 0, 4096, 128, 2048);
    kipost_kernel<<<4096, 128, 0, s1>>>(ki, iknw, iknb, fcos, fsin);
    gemm_bt<<<dim3(1, 32, 1), 256, 0, s1>>>(x, 2048, 0, iwp, 2048, 0, wts, 16, 0, 4096, 16, 2048);
    cudaStreamWaitEvent(s1, eQR, 0);
    gemm_bt<<<dim3(16, 32, 1), 256, 0, s1>>>(qr, 768, 0, iwqb, 768, 0, qi, 2048, 0, 4096, 2048, 768);
    rope_qi_kernel<<<(BS_*16*32 + 255)/256, 256, 0, s1>>>(qi, fcos, fsin);
    iscore_kernel<<<dim3(32, 12, 1), 256, 0, s1>>>(qi, ki, wts, iscore, 512);
    topk_kernel<<<1536, 256, 0, s1>>>(iscore, topkb, 512);
    cudaEventRecord(eT0, s1);
    iscore_kernel<<<dim3(32, 12, 1), 256, 0, s1>>>(qi + (long)S_*2048, ki + (long)S_*128,
                                                   wts + (long)S_*16, iscore + (long)S_*S_, 512);
    topk_kernel<<<1536, 256, 0, s1>>>(iscore + (long)S_*S_, topkb + (long)S_*ITOPK_, 512);
    cudaEventRecord(eT1, s1);

    // ---- s0 continues: q chain, qabs, early attention (s<512, both batches),
    //      then main attention per batch + output tail
    gemm_mma<<<dim3(24, 32, 1), 256, GM_SMEM, s0>>>(qr, 768, 0, wq_b, 768, 0, q, 3072, 0, 4096, 3072, 768);
    rope_q_kernel<<<(BS_*16*32 + 255)/256, 256, 0, s0>>>(q, fcos, fsin);
    cudaStreamWaitEvent(s0, eWT, 0);
    gemm_mma<<<dim3(4, 32, 16), 256, GM_SMEM, s0>>>(q, 3072, 192, wt, 128, 65536, qabs, 8192, 512,
                                                    4096, 512, 128);
    attn_tc<<<dim3(512, 2, 1), 512, AT_SMEM, s0>>>(qabs, q, khi, klo, topkb, omid, 0, 0);
    cudaStreamWaitEvent(s0, eT0, 0);
    attn_tc<<<dim3(1536, 1, 1), 512, AT_SMEM, s0>>>(qabs, q, khi, klo, topkb, omid, 0, 512);
    cudaStreamWaitEvent(s0, eT1, 0);
    attn_tc<<<dim3(1536, 1, 1), 512, AT_SMEM, s0>>>(qabs, q, khi, klo, topkb, omid, 1, 512);
    gemm_mma<<<dim3(1, 32, 16), 256, GM_SMEM, s0>>>(omid, 8192, 512, wkv_b + 128*512, 512, 256*512,
                                                    o2, 2048, 128, 4096, 128, 512);
    gemm_mma<<<dim3(16, 32, 1), 256, GM_SMEM, s0>>>(o2, 2048, 0, wo, 2048, 0, out, 2048, 0, 4096, 2048, 2048);
}